// round 5
// baseline (speedup 1.0000x reference)
#include <cuda_runtime.h>
#include <math.h>
#include <stdint.h>

// ---------------------------------------------------------------------------
// Problem constants: B=1, S=2048, H=4096, NH=32, NKV=8, HD=128
// ---------------------------------------------------------------------------
#define S_LEN 2048
#define HDIM  4096
#define NH    32
#define NKV   8
#define HD    128
#define SCALING 0.08838834764831843f  // 128^-0.5

// Device-global scratch (no runtime allocation allowed)
__device__ float g_hst[S_LEN * HDIM];          // hs rounded to tf32
__device__ float g_wqt[HDIM * HDIM];
__device__ float g_wkt[NKV * HD * HDIM];
__device__ float g_wvt[NKV * HD * HDIM];
__device__ float g_wot[HDIM * HDIM];
__device__ float g_q  [S_LEN * NH  * HD];
__device__ float g_k  [S_LEN * NKV * HD];
__device__ float g_v  [S_LEN * NKV * HD];
__device__ float g_vt [NKV * HD * S_LEN];      // V^T per kv-head, tf32-rounded
__device__ float g_ao [S_LEN * NH  * HD];
__device__ float g_wt [(size_t)NH * S_LEN * S_LEN];   // tf32-rounded weights
__device__ float g_w_scratch[(size_t)NH * S_LEN * S_LEN]; // fallback fp32 W

// ---------------------------------------------------------------------------
// Helpers
// ---------------------------------------------------------------------------
__device__ __forceinline__ uint32_t f2tf32u(float x) {
    uint32_t u;
    asm("cvt.rna.tf32.f32 %0, %1;" : "=r"(u) : "f"(x));
    return u;
}
__device__ __forceinline__ float tf32r(float x) { return __uint_as_float(f2tf32u(x)); }

__device__ __forceinline__ void mma_tf32(float* c, const uint32_t* a, const uint32_t* b) {
    asm volatile(
        "mma.sync.aligned.m16n8k8.row.col.f32.tf32.tf32.f32 "
        "{%0,%1,%2,%3}, {%4,%5,%6,%7}, {%8,%9}, {%0,%1,%2,%3};\n"
        : "+f"(c[0]), "+f"(c[1]), "+f"(c[2]), "+f"(c[3])
        : "r"(a[0]), "r"(a[1]), "r"(a[2]), "r"(a[3]), "r"(b[0]), "r"(b[1]));
}
__device__ __forceinline__ void ldsm4(uint32_t* r, uint32_t addr) {
    asm volatile("ldmatrix.sync.aligned.m8n8.x4.shared.b16 {%0,%1,%2,%3}, [%4];"
        : "=r"(r[0]), "=r"(r[1]), "=r"(r[2]), "=r"(r[3]) : "r"(addr));
}
__device__ __forceinline__ void cp16(uint32_t dst, const void* src) {
    asm volatile("cp.async.cg.shared.global [%0], [%1], 16;" :: "r"(dst), "l"(src));
}
#define CP_COMMIT() asm volatile("cp.async.commit_group;")
#define CP_WAIT1()  asm volatile("cp.async.wait_group 1;")

// ---------------------------------------------------------------------------
// Unified TF32 GEMM:  C[z] = alpha * A[z] @ B[z>>bShift]^T
// A[M,K] k-major (lda), B[N,K] k-major (ldb), C[M,N] (ldc).
// Inputs must already be tf32-rounded fp32. BM=BN=128, BK=16, 8 warps (2x4).
// mode: 0 = dense, 1 = causal block-skip (bx>by), 2 = K clipped to (by+1)*128.
// roundC: round outputs to tf32.
// Swizzled smem: 16B chunk (r,c) at byte (r*4 + (c ^ ((r>>1)&3)))*16.
// ---------------------------------------------------------------------------
#define BM 128
#define BN 128
#define TILE_B 8192        // one 128x16 fp32 tile
#define STAGE_B 16384      // A tile + B tile
#define NSTAGE 3

__global__ __launch_bounds__(256, 2) void mm_tf32(
    const float* __restrict__ A, const float* __restrict__ B, float* __restrict__ C,
    int K, int lda, int ldb, int ldc,
    long long bsA, long long bsB, int bShift, long long bsC,
    float alpha, int mode, int roundC)
{
    const int bx = blockIdx.x, by = blockIdx.y, bz = blockIdx.z;
    if (mode == 1 && bx > by) return;

    A += (long long)bz * bsA;
    B += (long long)(bz >> bShift) * bsB;
    C += (long long)bz * bsC;

    const int Ktot = (mode == 2) ? min(K, (by + 1) * BM) : K;
    const int NT = Ktot >> 4;

    __shared__ __align__(128) char smem[NSTAGE * STAGE_B];
    const uint32_t sb0 = (uint32_t)__cvta_generic_to_shared(smem);

    const int tid  = threadIdx.x;
    const int lane = tid & 31;
    const int w    = tid >> 5;
    const int wm   = w >> 2;     // 0..1
    const int wn   = w & 3;      // 0..3
    const int t4   = lane >> 2;  // 0..7
    const int l4   = lane & 3;   // 0..3

    // cp.async mapping: thread covers rows rr, rr+64 / 16B chunk cc of each tile
    const int rr = tid >> 2;
    const int cc = tid & 3;
    const uint32_t offT = (uint32_t)((rr * 4 + (cc ^ ((rr >> 1) & 3))) * 16);
    const float* gA = A + (long long)(by * BM + rr) * lda + cc * 4;
    const float* gB = B + (long long)(bx * BN + rr) * ldb + cc * 4;
    const long long sA64 = 64LL * lda;
    const long long sB64 = 64LL * ldb;

    // ldmatrix per-lane byte offsets (within stage), for ksteps 0 and 1
    uint32_t aoff[2], boff[2];
    {
        const int rowA = wm * 64 + (lane & 7) + (lane & 8);
        const int rowB = wn * 32 + (lane & 7) + ((lane >> 4) << 3);
        #pragma unroll
        for (int ks = 0; ks < 2; ks++) {
            const int chA = 2 * ks + (lane >> 4);
            const int chB = 2 * ks + ((lane >> 3) & 1);
            aoff[ks] = (uint32_t)((rowA * 4 + (chA ^ ((rowA >> 1) & 3))) * 16);
            boff[ks] = (uint32_t)(TILE_B + (rowB * 4 + (chB ^ ((rowB >> 1) & 3))) * 16);
        }
    }

    float acc[4][4][4];
    #pragma unroll
    for (int i = 0; i < 4; i++)
        #pragma unroll
        for (int j = 0; j < 4; j++)
            #pragma unroll
            for (int r = 0; r < 4; r++) acc[i][j][r] = 0.f;

    // Prologue: stages 0,1
    #pragma unroll
    for (int s = 0; s < 2; s++) {
        if (s < NT) {
            const uint32_t d = sb0 + s * STAGE_B;
            const float* a0 = gA + s * 16;
            const float* b0 = gB + s * 16;
            cp16(d + offT,                   a0);
            cp16(d + offT + 4096,            a0 + sA64);
            cp16(d + TILE_B + offT,          b0);
            cp16(d + TILE_B + offT + 4096,   b0 + sB64);
        }
        CP_COMMIT();
    }

    for (int t = 0; t < NT; t++) {
        CP_WAIT1();
        __syncthreads();
        const uint32_t sb = sb0 + (t % NSTAGE) * STAGE_B;

        #pragma unroll
        for (int ks = 0; ks < 2; ks++) {
            uint32_t a[4][4], b[2][4];
            #pragma unroll
            for (int mi = 0; mi < 4; mi++) ldsm4(a[mi], sb + aoff[ks] + mi * 1024);
            #pragma unroll
            for (int p = 0; p < 2; p++)   ldsm4(b[p],  sb + boff[ks] + p * 1024);
            #pragma unroll
            for (int mi = 0; mi < 4; mi++)
                #pragma unroll
                for (int ni = 0; ni < 4; ni++)
                    mma_tf32(acc[mi][ni], a[mi], &b[ni >> 1][(ni & 1) * 2]);
        }

        const int tn = t + 2;
        if (tn < NT) {
            const uint32_t d = sb0 + (tn % NSTAGE) * STAGE_B;
            const float* a0 = gA + tn * 16;
            const float* b0 = gB + tn * 16;
            cp16(d + offT,                  a0);
            cp16(d + offT + 4096,           a0 + sA64);
            cp16(d + TILE_B + offT,         b0);
            cp16(d + TILE_B + offT + 4096,  b0 + sB64);
        }
        CP_COMMIT();
    }

    // Epilogue
    #pragma unroll
    for (int mi = 0; mi < 4; mi++) {
        const int r0 = by * BM + wm * 64 + mi * 16 + t4;
        #pragma unroll
        for (int ni = 0; ni < 4; ni++) {
            const int c0 = bx * BN + wn * 32 + ni * 8 + 2 * l4;
            float v0 = acc[mi][ni][0] * alpha, v1 = acc[mi][ni][1] * alpha;
            float v2 = acc[mi][ni][2] * alpha, v3 = acc[mi][ni][3] * alpha;
            if (roundC) { v0 = tf32r(v0); v1 = tf32r(v1); v2 = tf32r(v2); v3 = tf32r(v3); }
            *reinterpret_cast<float2*>(&C[(long long)r0 * ldc + c0])       = make_float2(v0, v1);
            *reinterpret_cast<float2*>(&C[(long long)(r0 + 8) * ldc + c0]) = make_float2(v2, v3);
        }
    }
}

// ---------------------------------------------------------------------------
// Elementwise tf32 rounding: out[i] = tf32(in[i]). n multiple of 4.
// ---------------------------------------------------------------------------
__global__ void cvt_tf32(const float4* __restrict__ in, float4* __restrict__ out, int n4)
{
    int i = blockIdx.x * blockDim.x + threadIdx.x;
    if (i < n4) {
        float4 v = in[i];
        v.x = tf32r(v.x); v.y = tf32r(v.y); v.z = tf32r(v.z); v.w = tf32r(v.w);
        out[i] = v;
    }
}

// ---------------------------------------------------------------------------
// RoPE in place, output rounded to tf32.
// ---------------------------------------------------------------------------
__global__ void rope_kernel(float* __restrict__ x,
                            const float* __restrict__ cosb,
                            const float* __restrict__ sinb, int nh)
{
    int i = blockIdx.x * blockDim.x + threadIdx.x;
    int total = S_LEN * nh * 64;
    if (i >= total) return;
    int d = i & 63;
    int h = (i >> 6) % nh;
    int s = i / (64 * nh);
    float c1 = cosb[s * HD + d];
    float s1 = sinb[s * HD + d];
    float c2 = cosb[s * HD + d + 64];
    float s2 = sinb[s * HD + d + 64];
    float* p = x + (long long)s * nh * HD + h * HD;
    float x1 = p[d];
    float x2 = p[d + 64];
    p[d]      = tf32r(x1 * c1 - x2 * s1);
    p[d + 64] = tf32r(x2 * c2 + x1 * s2);
}

// ---------------------------------------------------------------------------
// V transpose: g_v[s][h*128+d] -> g_vt[h][d][s], rounded to tf32.
// grid (64, 4, 8), block (32, 8)
// ---------------------------------------------------------------------------
__global__ void transpose_v(const float* __restrict__ v, float* __restrict__ vt)
{
    __shared__ float tile[32][33];
    const int h  = blockIdx.z;
    const int s0 = blockIdx.x * 32;
    const int d0 = blockIdx.y * 32;
    const int tx = threadIdx.x, ty = threadIdx.y;
    #pragma unroll
    for (int j = 0; j < 4; j++)
        tile[ty + j * 8][tx] = v[(long long)(s0 + ty + j * 8) * (NKV * HD) + h * HD + d0 + tx];
    __syncthreads();
    #pragma unroll
    for (int j = 0; j < 4; j++)
        vt[(long long)h * HD * S_LEN + (long long)(d0 + ty + j * 8) * S_LEN + s0 + tx] =
            tf32r(tile[tx][ty + j * 8]);
}

// ---------------------------------------------------------------------------
// Causal softmax: reads fp32 scores row, writes fp32 W (checked output) and
// tf32-rounded Wt (GEMM operand). Zeros for k > q.
// ---------------------------------------------------------------------------
__global__ __launch_bounds__(256) void softmax_causal(float* __restrict__ W,
                                                      float* __restrict__ Wt)
{
    const int q = blockIdx.x;
    const int h = blockIdx.y;
    const long long off = ((long long)h * S_LEN + q) * S_LEN;
    float* row  = W  + off;
    float* rowt = Wt + off;
    const int L = q + 1;
    const int tid = threadIdx.x;
    __shared__ float red[32];

    float vals[8];
    int cnt = 0;

    float mx = -3.402823e38f;
    for (int k = tid; k < L; k += 256) {
        float x = row[k];
        vals[cnt++] = x;
        mx = fmaxf(mx, x);
    }
    #pragma unroll
    for (int o = 16; o; o >>= 1) mx = fmaxf(mx, __shfl_xor_sync(0xffffffffu, mx, o));
    if ((tid & 31) == 0) red[tid >> 5] = mx;
    __syncthreads();
    if (tid < 32) {
        float w2 = (tid < 8) ? red[tid] : -3.402823e38f;
        #pragma unroll
        for (int o = 4; o; o >>= 1) w2 = fmaxf(w2, __shfl_xor_sync(0xffffffffu, w2, o));
        if (tid == 0) red[0] = w2;
    }
    __syncthreads();
    mx = red[0];
    __syncthreads();

    float s = 0.f;
    for (int i = 0; i < cnt; i++) {
        float e = expf(vals[i] - mx);
        vals[i] = e;
        s += e;
    }
    #pragma unroll
    for (int o = 16; o; o >>= 1) s += __shfl_xor_sync(0xffffffffu, s, o);
    if ((tid & 31) == 0) red[tid >> 5] = s;
    __syncthreads();
    if (tid < 32) {
        float w2 = (tid < 8) ? red[tid] : 0.f;
        #pragma unroll
        for (int o = 4; o; o >>= 1) w2 += __shfl_xor_sync(0xffffffffu, w2, o);
        if (tid == 0) red[0] = w2;
    }
    __syncthreads();
    const float inv = 1.f / red[0];

    int i = 0;
    for (int k = tid; k < S_LEN; k += 256) {
        float val = (k < L) ? vals[i++] * inv : 0.f;
        row[k]  = val;
        rowt[k] = tf32r(val);
    }
}

// ---------------------------------------------------------------------------
extern "C" void kernel_launch(void* const* d_in, const int* in_sizes, int n_in,
                              void* d_out, int out_size)
{
    const float* hs   = (const float*)d_in[0];
    const float* wq   = (const float*)d_in[1];
    const float* wk   = (const float*)d_in[2];
    const float* wv   = (const float*)d_in[3];
    const float* wo   = (const float*)d_in[4];
    const float* cosb = (const float*)d_in[5];
    const float* sinb = (const float*)d_in[6];
    (void)in_sizes; (void)n_in;

    float* out = (float*)d_out;

    const long long OUT_ELEMS = (long long)S_LEN * NH * HD;
    const long long W_ELEMS   = (long long)NH * S_LEN * S_LEN;

    float *hst, *wqt, *wkt, *wvt, *wot, *qp, *kp, *vp, *vtp, *aop, *wtp, *wsc;
    cudaGetSymbolAddress((void**)&hst, g_hst);
    cudaGetSymbolAddress((void**)&wqt, g_wqt);
    cudaGetSymbolAddress((void**)&wkt, g_wkt);
    cudaGetSymbolAddress((void**)&wvt, g_wvt);
    cudaGetSymbolAddress((void**)&wot, g_wot);
    cudaGetSymbolAddress((void**)&qp,  g_q);
    cudaGetSymbolAddress((void**)&kp,  g_k);
    cudaGetSymbolAddress((void**)&vp,  g_v);
    cudaGetSymbolAddress((void**)&vtp, g_vt);
    cudaGetSymbolAddress((void**)&aop, g_ao);
    cudaGetSymbolAddress((void**)&wtp, g_wt);
    cudaGetSymbolAddress((void**)&wsc, g_w_scratch);

    float* W = ((long long)out_size >= OUT_ELEMS + W_ELEMS) ? (out + OUT_ELEMS) : wsc;

    // 0) tf32 pre-rounding of inputs
    {
        int n;
        n = S_LEN * HDIM / 4;        cvt_tf32<<<(n + 255) / 256, 256>>>((const float4*)hs, (float4*)hst, n);
        n = HDIM * HDIM / 4;         cvt_tf32<<<(n + 255) / 256, 256>>>((const float4*)wq, (float4*)wqt, n);
        n = NKV * HD * HDIM / 4;     cvt_tf32<<<(n + 255) / 256, 256>>>((const float4*)wk, (float4*)wkt, n);
        n = NKV * HD * HDIM / 4;     cvt_tf32<<<(n + 255) / 256, 256>>>((const float4*)wv, (float4*)wvt, n);
        n = HDIM * HDIM / 4;         cvt_tf32<<<(n + 255) / 256, 256>>>((const float4*)wo, (float4*)wot, n);
    }

    // 1) QKV projections
    mm_tf32<<<dim3(NH * HD / BN,  S_LEN / BM), 256>>>(hst, wqt, qp,
        HDIM, HDIM, HDIM, NH * HD,  0, 0, 0, 0, 1.f, 0, 0);
    mm_tf32<<<dim3(NKV * HD / BN, S_LEN / BM), 256>>>(hst, wkt, kp,
        HDIM, HDIM, HDIM, NKV * HD, 0, 0, 0, 0, 1.f, 0, 0);
    mm_tf32<<<dim3(NKV * HD / BN, S_LEN / BM), 256>>>(hst, wvt, vp,
        HDIM, HDIM, HDIM, NKV * HD, 0, 0, 0, 0, 1.f, 0, 0);

    // 2) RoPE (rounds Q, K to tf32)
    rope_kernel<<<(S_LEN * NH  * 64 + 255) / 256, 256>>>(qp, cosb, sinb, NH);
    rope_kernel<<<(S_LEN * NKV * 64 + 255) / 256, 256>>>(kp, cosb, sinb, NKV);

    // 2b) V transpose (rounds to tf32)
    transpose_v<<<dim3(S_LEN / 32, HD / 32, NKV), dim3(32, 8)>>>(vp, vtp);

    // 3) Scores: Q_h @ K_{h/4}^T * scaling, causal block-skip
    mm_tf32<<<dim3(S_LEN / BN, S_LEN / BM, NH), 256>>>(qp, kp, W,
        HD, NH * HD, NKV * HD, S_LEN,
        HD, HD, 2, (long long)S_LEN * S_LEN, SCALING, 1, 0);

    // 4) Softmax -> W (fp32 output) + Wt (tf32 operand)
    softmax_causal<<<dim3(S_LEN, NH), 256>>>(W, wtp);

    // 5) attn_out = W_h @ (V^T_{h/4})^T with K clipped to (by+1)*128
    mm_tf32<<<dim3(1, S_LEN / BM, NH), 256>>>(wtp, vtp, aop,
        S_LEN, S_LEN, S_LEN, NH * HD,
        (long long)S_LEN * S_LEN, (long long)HD * S_LEN, 2, HD, 1.f, 2, 1);

    // 6) out = attn_out @ wo^T
    mm_tf32<<<dim3(NH * HD / BN, S_LEN / BM), 256>>>(aop, wot, out,
        HDIM, HDIM, HDIM, NH * HD, 0, 0, 0, 0, 1.f, 0, 0);
}

// round 7
// speedup vs baseline: 1.0716x; 1.0716x over previous
#include <cuda_runtime.h>
#include <math.h>
#include <stdint.h>

// ---------------------------------------------------------------------------
// Problem constants: B=1, S=2048, H=4096, NH=32, NKV=8, HD=128
// ---------------------------------------------------------------------------
#define S_LEN 2048
#define HDIM  4096
#define NH    32
#define NKV   8
#define HD    128
#define SCALING 0.08838834764831843f  // 128^-0.5

// Device-global scratch (no runtime allocation allowed)
__device__ float g_q  [S_LEN * NH  * HD];
__device__ float g_k  [S_LEN * NKV * HD];
__device__ float g_v  [S_LEN * NKV * HD];
__device__ float g_vt [NKV * HD * S_LEN];      // V^T per kv-head
__device__ float g_ao [S_LEN * NH  * HD];
__device__ float g_w_scratch[(size_t)NH * S_LEN * S_LEN]; // fallback fp32 W

// ---------------------------------------------------------------------------
// Helpers
// ---------------------------------------------------------------------------
__device__ __forceinline__ uint32_t f2tf32u(float x) {
    uint32_t u;
    asm("cvt.rna.tf32.f32 %0, %1;" : "=r"(u) : "f"(x));
    return u;
}
__device__ __forceinline__ float tf32r(float x) { return __uint_as_float(f2tf32u(x)); }

__device__ __forceinline__ void cvt4(uint32_t* r) {
    r[0] = f2tf32u(__uint_as_float(r[0]));
    r[1] = f2tf32u(__uint_as_float(r[1]));
    r[2] = f2tf32u(__uint_as_float(r[2]));
    r[3] = f2tf32u(__uint_as_float(r[3]));
}

__device__ __forceinline__ void mma_tf32(float* c, const uint32_t* a, const uint32_t* b) {
    asm volatile(
        "mma.sync.aligned.m16n8k8.row.col.f32.tf32.tf32.f32 "
        "{%0,%1,%2,%3}, {%4,%5,%6,%7}, {%8,%9}, {%0,%1,%2,%3};\n"
        : "+f"(c[0]), "+f"(c[1]), "+f"(c[2]), "+f"(c[3])
        : "r"(a[0]), "r"(a[1]), "r"(a[2]), "r"(a[3]), "r"(b[0]), "r"(b[1]));
}
__device__ __forceinline__ void ldsm4(uint32_t* r, uint32_t addr) {
    asm volatile("ldmatrix.sync.aligned.m8n8.x4.shared.b16 {%0,%1,%2,%3}, [%4];"
        : "=r"(r[0]), "=r"(r[1]), "=r"(r[2]), "=r"(r[3]) : "r"(addr));
}
__device__ __forceinline__ void cp16(uint32_t dst, const void* src) {
    asm volatile("cp.async.cg.shared.global [%0], [%1], 16;" :: "r"(dst), "l"(src));
}
#define CP_COMMIT() asm volatile("cp.async.commit_group;")
#define CP_WAIT1()  asm volatile("cp.async.wait_group 1;")

// ---------------------------------------------------------------------------
// TF32 GEMM (raw fp32 inputs, tf32 conversion post-ldmatrix in registers):
//   C[z] = alpha * A[z] @ B[z>>bShift]^T
// A[M,K] k-major (lda), B[N,K] k-major (ldb), C[M,N] (ldc).
// BM=BN=128, BK=16, 512 threads, 16 warps (4x4), warp tile 32x32.
// mode: 0 = dense, 1 = causal block-skip (bx>by), 2 = K clipped to (by+1)*128.
// Swizzled smem: 16B chunk (r,c) at byte (r*4 + (c ^ ((r>>1)&3)))*16.
// ---------------------------------------------------------------------------
#define BM 128
#define BN 128
#define TILE_B 8192        // one 128x16 fp32 tile
#define STAGE_B 16384      // A tile + B tile
#define NSTAGE 3

__global__ __launch_bounds__(512) void mm_tf32(
    const float* __restrict__ A, const float* __restrict__ B, float* __restrict__ C,
    int K, int lda, int ldb, int ldc,
    long long bsA, long long bsB, int bShift, long long bsC,
    float alpha, int mode)
{
    const int bx = blockIdx.x, by = blockIdx.y, bz = blockIdx.z;
    if (mode == 1 && bx > by) return;

    A += (long long)bz * bsA;
    B += (long long)(bz >> bShift) * bsB;
    C += (long long)bz * bsC;

    const int Ktot = (mode == 2) ? min(K, (by + 1) * BM) : K;
    const int NT = Ktot >> 4;

    __shared__ __align__(128) char smem[NSTAGE * STAGE_B];
    const uint32_t sb0 = (uint32_t)__cvta_generic_to_shared(smem);

    const int tid  = threadIdx.x;
    const int lane = tid & 31;
    const int w    = tid >> 5;
    const int wm   = w >> 2;     // 0..3
    const int wn   = w & 3;      // 0..3
    const int t4   = lane >> 2;  // 0..7
    const int l4   = lane & 3;   // 0..3

    // cp.async mapping: thread covers row rr, 16B chunk cc of each tile
    const int rr = tid >> 2;          // 0..127
    const int cc = tid & 3;           // 0..3
    const uint32_t offT = (uint32_t)((rr * 4 + (cc ^ ((rr >> 1) & 3))) * 16);
    const float* gA = A + (long long)(by * BM + rr) * lda + cc * 4;
    const float* gB = B + (long long)(bx * BN + rr) * ldb + cc * 4;

    // ldmatrix per-lane byte offsets (within stage), ksteps 0 and 1
    uint32_t aoff[2], boff[2];
    {
        const int rowA = wm * 32 + (lane & 7) + (lane & 8);
        const int rowB = wn * 32 + (lane & 7) + ((lane >> 4) << 3);
        #pragma unroll
        for (int ks = 0; ks < 2; ks++) {
            const int chA = 2 * ks + (lane >> 4);
            const int chB = 2 * ks + ((lane >> 3) & 1);
            aoff[ks] = (uint32_t)((rowA * 4 + (chA ^ ((rowA >> 1) & 3))) * 16);
            boff[ks] = (uint32_t)(TILE_B + (rowB * 4 + (chB ^ ((rowB >> 1) & 3))) * 16);
        }
    }

    float acc[2][4][4];
    #pragma unroll
    for (int i = 0; i < 2; i++)
        #pragma unroll
        for (int j = 0; j < 4; j++)
            #pragma unroll
            for (int r = 0; r < 4; r++) acc[i][j][r] = 0.f;

    // Prologue: stages 0,1
    #pragma unroll
    for (int s = 0; s < 2; s++) {
        if (s < NT) {
            const uint32_t d = sb0 + s * STAGE_B;
            cp16(d + offT,          gA + s * 16);
            cp16(d + TILE_B + offT, gB + s * 16);
        }
        CP_COMMIT();
    }

    for (int t = 0; t < NT; t++) {
        CP_WAIT1();
        __syncthreads();
        const uint32_t sb = sb0 + (t % NSTAGE) * STAGE_B;

        #pragma unroll
        for (int ks = 0; ks < 2; ks++) {
            uint32_t a[2][4], b[2][4];
            #pragma unroll
            for (int mi = 0; mi < 2; mi++) { ldsm4(a[mi], sb + aoff[ks] + mi * 1024); cvt4(a[mi]); }
            #pragma unroll
            for (int p = 0; p < 2; p++)    { ldsm4(b[p],  sb + boff[ks] + p * 1024);  cvt4(b[p]); }
            #pragma unroll
            for (int mi = 0; mi < 2; mi++)
                #pragma unroll
                for (int ni = 0; ni < 4; ni++)
                    mma_tf32(acc[mi][ni], a[mi], &b[ni >> 1][(ni & 1) * 2]);
        }

        const int tn = t + 2;
        if (tn < NT) {
            const uint32_t d = sb0 + (tn % NSTAGE) * STAGE_B;
            cp16(d + offT,          gA + tn * 16);
            cp16(d + TILE_B + offT, gB + tn * 16);
        }
        CP_COMMIT();
    }

    // Epilogue
    #pragma unroll
    for (int mi = 0; mi < 2; mi++) {
        const int r0 = by * BM + wm * 32 + mi * 16 + t4;
        #pragma unroll
        for (int ni = 0; ni < 4; ni++) {
            const int c0 = bx * BN + wn * 32 + ni * 8 + 2 * l4;
            *reinterpret_cast<float2*>(&C[(long long)r0 * ldc + c0]) =
                make_float2(acc[mi][ni][0] * alpha, acc[mi][ni][1] * alpha);
            *reinterpret_cast<float2*>(&C[(long long)(r0 + 8) * ldc + c0]) =
                make_float2(acc[mi][ni][2] * alpha, acc[mi][ni][3] * alpha);
        }
    }
}

// ---------------------------------------------------------------------------
// RoPE in place (fp32; GEMMs convert to tf32 in-register downstream)
// ---------------------------------------------------------------------------
__global__ void rope_kernel(float* __restrict__ x,
                            const float* __restrict__ cosb,
                            const float* __restrict__ sinb, int nh)
{
    int i = blockIdx.x * blockDim.x + threadIdx.x;
    int total = S_LEN * nh * 64;
    if (i >= total) return;
    int d = i & 63;
    int h = (i >> 6) % nh;
    int s = i / (64 * nh);
    float c1 = cosb[s * HD + d];
    float s1 = sinb[s * HD + d];
    float c2 = cosb[s * HD + d + 64];
    float s2 = sinb[s * HD + d + 64];
    float* p = x + (long long)s * nh * HD + h * HD;
    float x1 = p[d];
    float x2 = p[d + 64];
    p[d]      = x1 * c1 - x2 * s1;
    p[d + 64] = x2 * c2 + x1 * s2;
}

// ---------------------------------------------------------------------------
// V transpose: g_v[s][h*128+d] -> g_vt[h][d][s]
// grid (64, 4, 8), block (32, 8)
// ---------------------------------------------------------------------------
__global__ void transpose_v(const float* __restrict__ v, float* __restrict__ vt)
{
    __shared__ float tile[32][33];
    const int h  = blockIdx.z;
    const int s0 = blockIdx.x * 32;
    const int d0 = blockIdx.y * 32;
    const int tx = threadIdx.x, ty = threadIdx.y;
    #pragma unroll
    for (int j = 0; j < 4; j++)
        tile[ty + j * 8][tx] = v[(long long)(s0 + ty + j * 8) * (NKV * HD) + h * HD + d0 + tx];
    __syncthreads();
    #pragma unroll
    for (int j = 0; j < 4; j++)
        vt[(long long)h * HD * S_LEN + (long long)(d0 + ty + j * 8) * S_LEN + s0 + tx] =
            tile[tx][ty + j * 8];
}

// ---------------------------------------------------------------------------
// Causal softmax in place over W[NH, S, S]. Zeros for k > q.
// ---------------------------------------------------------------------------
__global__ __launch_bounds__(256) void softmax_causal(float* __restrict__ W)
{
    const int q = blockIdx.x;
    const int h = blockIdx.y;
    float* row = W + ((long long)h * S_LEN + q) * S_LEN;
    const int L = q + 1;
    const int tid = threadIdx.x;
    __shared__ float red[32];

    float vals[8];
    int cnt = 0;

    float mx = -3.402823e38f;
    for (int k = tid; k < L; k += 256) {
        float x = row[k];
        vals[cnt++] = x;
        mx = fmaxf(mx, x);
    }
    #pragma unroll
    for (int o = 16; o; o >>= 1) mx = fmaxf(mx, __shfl_xor_sync(0xffffffffu, mx, o));
    if ((tid & 31) == 0) red[tid >> 5] = mx;
    __syncthreads();
    if (tid < 32) {
        float w2 = (tid < 8) ? red[tid] : -3.402823e38f;
        #pragma unroll
        for (int o = 4; o; o >>= 1) w2 = fmaxf(w2, __shfl_xor_sync(0xffffffffu, w2, o));
        if (tid == 0) red[0] = w2;
    }
    __syncthreads();
    mx = red[0];
    __syncthreads();

    float s = 0.f;
    for (int i = 0; i < cnt; i++) {
        float e = expf(vals[i] - mx);
        vals[i] = e;
        s += e;
    }
    #pragma unroll
    for (int o = 16; o; o >>= 1) s += __shfl_xor_sync(0xffffffffu, s, o);
    if ((tid & 31) == 0) red[tid >> 5] = s;
    __syncthreads();
    if (tid < 32) {
        float w2 = (tid < 8) ? red[tid] : 0.f;
        #pragma unroll
        for (int o = 4; o; o >>= 1) w2 += __shfl_xor_sync(0xffffffffu, w2, o);
        if (tid == 0) red[0] = w2;
    }
    __syncthreads();
    const float inv = 1.f / red[0];

    int i = 0;
    for (int k = tid; k < S_LEN; k += 256) {
        row[k] = (k < L) ? vals[i++] * inv : 0.f;
    }
}

// ---------------------------------------------------------------------------
extern "C" void kernel_launch(void* const* d_in, const int* in_sizes, int n_in,
                              void* d_out, int out_size)
{
    const float* hs   = (const float*)d_in[0];
    const float* wq   = (const float*)d_in[1];
    const float* wk   = (const float*)d_in[2];
    const float* wv   = (const float*)d_in[3];
    const float* wo   = (const float*)d_in[4];
    const float* cosb = (const float*)d_in[5];
    const float* sinb = (const float*)d_in[6];
    (void)in_sizes; (void)n_in;

    float* out = (float*)d_out;

    const long long OUT_ELEMS = (long long)S_LEN * NH * HD;
    const long long W_ELEMS   = (long long)NH * S_LEN * S_LEN;

    float *qp, *kp, *vp, *vtp, *aop, *wsc;
    cudaGetSymbolAddress((void**)&qp,  g_q);
    cudaGetSymbolAddress((void**)&kp,  g_k);
    cudaGetSymbolAddress((void**)&vp,  g_v);
    cudaGetSymbolAddress((void**)&vtp, g_vt);
    cudaGetSymbolAddress((void**)&aop, g_ao);
    cudaGetSymbolAddress((void**)&wsc, g_w_scratch);

    float* W = ((long long)out_size >= OUT_ELEMS + W_ELEMS) ? (out + OUT_ELEMS) : wsc;

    // 1) QKV projections: X @ Wx^T  (in-register tf32 conversion)
    mm_tf32<<<dim3(NH * HD / BN,  S_LEN / BM), 512>>>(hs, wq, qp,
        HDIM, HDIM, HDIM, NH * HD,  0, 0, 0, 0, 1.f, 0);
    mm_tf32<<<dim3(NKV * HD / BN, S_LEN / BM), 512>>>(hs, wk, kp,
        HDIM, HDIM, HDIM, NKV * HD, 0, 0, 0, 0, 1.f, 0);
    mm_tf32<<<dim3(NKV * HD / BN, S_LEN / BM), 512>>>(hs, wv, vp,
        HDIM, HDIM, HDIM, NKV * HD, 0, 0, 0, 0, 1.f, 0);

    // 2) RoPE on Q, K
    rope_kernel<<<(S_LEN * NH  * 64 + 255) / 256, 256>>>(qp, cosb, sinb, NH);
    rope_kernel<<<(S_LEN * NKV * 64 + 255) / 256, 256>>>(kp, cosb, sinb, NKV);

    // 2b) V transpose
    transpose_v<<<dim3(S_LEN / 32, HD / 32, NKV), dim3(32, 8)>>>(vp, vtp);

    // 3) Scores: Q_h @ K_{h/4}^T * scaling, causal block-skip
    mm_tf32<<<dim3(S_LEN / BN, S_LEN / BM, NH), 512>>>(qp, kp, W,
        HD, NH * HD, NKV * HD, S_LEN,
        HD, HD, 2, (long long)S_LEN * S_LEN, SCALING, 1);

    // 4) Softmax in place
    softmax_causal<<<dim3(S_LEN, NH), 256>>>(W);

    // 5) attn_out = W_h @ (V^T_{h/4})^T with K clipped to (by+1)*128
    mm_tf32<<<dim3(1, S_LEN / BM, NH), 512>>>(W, vtp, aop,
        S_LEN, S_LEN, S_LEN, NH * HD,
        (long long)S_LEN * S_LEN, (long long)HD * S_LEN, 2, HD, 1.f, 2);

    // 6) out = attn_out @ wo^T
    mm_tf32<<<dim3(NH * HD / BN, S_LEN / BM), 512>>>(aop, wo, out,
        HDIM, HDIM, HDIM, NH * HD, 0, 0, 0, 0, 1.f, 0);
}

// round 9
// speedup vs baseline: 1.9007x; 1.7737x over previous
#include <cuda_runtime.h>
#include <cuda_fp16.h>
#include <math.h>
#include <stdint.h>

// ---------------------------------------------------------------------------
// Problem constants: B=1, S=2048, H=4096, NH=32, NKV=8, HD=128
// ---------------------------------------------------------------------------
#define S_LEN 2048
#define HDIM  4096
#define NH    32
#define NKV   8
#define HD    128
#define SCALING 0.08838834764831843f  // 128^-0.5

// Device-global scratch (no runtime allocation allowed)
__device__ __half g_hsh[S_LEN * HDIM];
__device__ __half g_wqh[HDIM * HDIM];
__device__ __half g_wkh[NKV * HD * HDIM];
__device__ __half g_wvh[NKV * HD * HDIM];
__device__ __half g_woh[HDIM * HDIM];
__device__ float  g_q  [S_LEN * NH  * HD];   // fp32 proj outputs (pre-rope)
__device__ float  g_k  [S_LEN * NKV * HD];
__device__ float  g_v  [S_LEN * NKV * HD];
__device__ __half g_qh [S_LEN * NH  * HD];   // fp16 operands post-rope
__device__ __half g_kh [S_LEN * NKV * HD];
__device__ __half g_vt [NKV * HD * S_LEN];   // V^T per kv-head, fp16
__device__ __half g_aoh[S_LEN * NH  * HD];   // attn_out fp16
__device__ __half g_wh [(size_t)NH * S_LEN * S_LEN];      // fp16 weights operand
__device__ float  g_w_scratch[(size_t)NH * S_LEN * S_LEN]; // fallback fp32 W

// ---------------------------------------------------------------------------
// Helpers
// ---------------------------------------------------------------------------
__device__ __forceinline__ void mma_f16(float* c, const uint32_t* a,
                                        uint32_t b0, uint32_t b1) {
    asm volatile(
        "mma.sync.aligned.m16n8k16.row.col.f32.f16.f16.f32 "
        "{%0,%1,%2,%3}, {%4,%5,%6,%7}, {%8,%9}, {%0,%1,%2,%3};\n"
        : "+f"(c[0]), "+f"(c[1]), "+f"(c[2]), "+f"(c[3])
        : "r"(a[0]), "r"(a[1]), "r"(a[2]), "r"(a[3]), "r"(b0), "r"(b1));
}
__device__ __forceinline__ void ldsm4(uint32_t* r, uint32_t addr) {
    asm volatile("ldmatrix.sync.aligned.m8n8.x4.shared.b16 {%0,%1,%2,%3}, [%4];"
        : "=r"(r[0]), "=r"(r[1]), "=r"(r[2]), "=r"(r[3]) : "r"(addr));
}
__device__ __forceinline__ void cp16(uint32_t dst, const void* src) {
    asm volatile("cp.async.cg.shared.global [%0], [%1], 16;" :: "r"(dst), "l"(src));
}
#define CP_COMMIT() asm volatile("cp.async.commit_group;")
#define CP_WAIT1()  asm volatile("cp.async.wait_group 1;")

// ---------------------------------------------------------------------------
// FP16 GEMM (fp16 operands, fp32 accumulate):  C[z] = alpha * A[z] @ B[z>>bShift]^T
// A[M,K] k-major fp16 (lda), B[N,K] k-major fp16 (ldb).
// C: fp32 (outF16=0) or fp16 (outF16=1), ldc.
// BM=BN=128, BK=32, 512 threads, 16 warps (4x4), warp tile 32x32.
// mode: 0 dense, 1 causal block-skip (bx>by), 2 K clipped to (by+1)*128.
// Smem tile: 128 rows x 64B, 16B chunk c of row r at c ^ ((r>>1)&3)  (Sw<2,3,3>).
// ---------------------------------------------------------------------------
#define BM 128
#define BN 128
#define TILE_B 8192        // one 128x32 fp16 tile
#define STAGE_B 16384      // A tile + B tile
#define NSTAGE 3

__global__ __launch_bounds__(512) void mm_f16(
    const __half* __restrict__ A, const __half* __restrict__ B, void* __restrict__ Cv,
    int K, int lda, int ldb, int ldc,
    long long bsA, long long bsB, int bShift, long long bsC,
    float alpha, int mode, int outF16)
{
    const int bx = blockIdx.x, by = blockIdx.y, bz = blockIdx.z;
    if (mode == 1 && bx > by) return;

    A += (long long)bz * bsA;
    B += (long long)(bz >> bShift) * bsB;

    const int Ktot = (mode == 2) ? min(K, (by + 1) * BM) : K;
    const int NT = Ktot >> 5;   // K-chunks of 32

    __shared__ __align__(128) char smem[NSTAGE * STAGE_B];
    const uint32_t sb0 = (uint32_t)__cvta_generic_to_shared(smem);

    const int tid  = threadIdx.x;
    const int lane = tid & 31;
    const int w    = tid >> 5;
    const int wm   = w >> 2;     // 0..3
    const int wn   = w & 3;      // 0..3
    const int t4   = lane >> 2;  // 0..7
    const int l4   = lane & 3;   // 0..3

    // Loader: thread covers row rr, 16B chunk cc (8 fp16) of each tile.
    const int rr = tid >> 2;          // 0..127
    const int cc = tid & 3;           // 0..3
    const uint32_t offT = (uint32_t)(rr * 64 + ((cc ^ ((rr >> 1) & 3)) << 4));
    const __half* gA = A + (long long)(by * BM + rr) * lda + cc * 8;
    const __half* gB = B + (long long)(bx * BN + rr) * ldb + cc * 8;

    // ldmatrix per-lane byte offsets (within stage) for ksteps 0,1.
    // A: 16x16 tile at rows wm*32+mi*16; B: 16 rows at wn*32+p*16.
    uint32_t aoff[2], boff[2];
    {
        const int ra = wm * 32 + (lane & 15);      // + mi*16 added via +1024
        const int rb = wn * 32 + (lane & 15);      // + p*16  added via +1024
        #pragma unroll
        for (int ks = 0; ks < 2; ks++) {
            const int cha = ks * 2 + (lane >> 4);
            aoff[ks] = (uint32_t)(ra * 64 + ((cha ^ ((ra >> 1) & 3)) << 4));
            boff[ks] = (uint32_t)(TILE_B + rb * 64 + ((cha ^ ((rb >> 1) & 3)) << 4));
        }
    }

    float acc[2][4][4];
    #pragma unroll
    for (int i = 0; i < 2; i++)
        #pragma unroll
        for (int j = 0; j < 4; j++)
            #pragma unroll
            for (int r = 0; r < 4; r++) acc[i][j][r] = 0.f;

    // Prologue: stages 0,1
    #pragma unroll
    for (int s = 0; s < 2; s++) {
        if (s < NT) {
            const uint32_t d = sb0 + s * STAGE_B + offT;
            cp16(d,          gA + s * 32);
            cp16(d + TILE_B, gB + s * 32);
        }
        CP_COMMIT();
    }

    for (int t = 0; t < NT; t++) {
        CP_WAIT1();
        __syncthreads();
        const uint32_t sb = sb0 + (t % NSTAGE) * STAGE_B;

        #pragma unroll
        for (int ks = 0; ks < 2; ks++) {
            uint32_t a[2][4], b[2][4];
            #pragma unroll
            for (int mi = 0; mi < 2; mi++) ldsm4(a[mi], sb + aoff[ks] + mi * 1024);
            #pragma unroll
            for (int p = 0; p < 2; p++)    ldsm4(b[p],  sb + boff[ks] + p * 1024);
            // b[p]: {rows0-7 k0-7, rows8-15 k0-7, rows0-7 k8-15, rows8-15 k8-15}
            #pragma unroll
            for (int mi = 0; mi < 2; mi++)
                #pragma unroll
                for (int p = 0; p < 2; p++) {
                    mma_f16(acc[mi][p * 2 + 0], a[mi], b[p][0], b[p][2]);
                    mma_f16(acc[mi][p * 2 + 1], a[mi], b[p][1], b[p][3]);
                }
        }

        const int tn = t + 2;
        if (tn < NT) {
            const uint32_t d = sb0 + (tn % NSTAGE) * STAGE_B + offT;
            cp16(d,          gA + tn * 32);
            cp16(d + TILE_B, gB + tn * 32);
        }
        CP_COMMIT();
    }

    // Epilogue
    #pragma unroll
    for (int mi = 0; mi < 2; mi++) {
        const int r0 = by * BM + wm * 32 + mi * 16 + t4;
        #pragma unroll
        for (int ni = 0; ni < 4; ni++) {
            const int c0 = bx * BN + wn * 32 + ni * 8 + 2 * l4;
            float v0 = acc[mi][ni][0] * alpha, v1 = acc[mi][ni][1] * alpha;
            float v2 = acc[mi][ni][2] * alpha, v3 = acc[mi][ni][3] * alpha;
            if (outF16) {
                __half* C = (__half*)Cv + (long long)bz * bsC;
                *reinterpret_cast<__half2*>(&C[(long long)r0 * ldc + c0]) =
                    __floats2half2_rn(v0, v1);
                *reinterpret_cast<__half2*>(&C[(long long)(r0 + 8) * ldc + c0]) =
                    __floats2half2_rn(v2, v3);
            } else {
                float* C = (float*)Cv + (long long)bz * bsC;
                *reinterpret_cast<float2*>(&C[(long long)r0 * ldc + c0]) = make_float2(v0, v1);
                *reinterpret_cast<float2*>(&C[(long long)(r0 + 8) * ldc + c0]) = make_float2(v2, v3);
            }
        }
    }
}

// ---------------------------------------------------------------------------
// fp32 -> fp16 conversion (rne), 4 elements/thread
// ---------------------------------------------------------------------------
__global__ void cvt_f16(const float4* __restrict__ in, __half2* __restrict__ out, int n4)
{
    int i = blockIdx.x * blockDim.x + threadIdx.x;
    if (i < n4) {
        float4 v = in[i];
        out[i * 2 + 0] = __floats2half2_rn(v.x, v.y);
        out[i * 2 + 1] = __floats2half2_rn(v.z, v.w);
    }
}

// ---------------------------------------------------------------------------
// RoPE: reads fp32 proj, writes fp16 operand buffer.
// ---------------------------------------------------------------------------
__global__ void rope_kernel(const float* __restrict__ x, __half* __restrict__ xo,
                            const float* __restrict__ cosb,
                            const float* __restrict__ sinb, int nh)
{
    int i = blockIdx.x * blockDim.x + threadIdx.x;
    int total = S_LEN * nh * 64;
    if (i >= total) return;
    int d = i & 63;
    int h = (i >> 6) % nh;
    int s = i / (64 * nh);
    float c1 = cosb[s * HD + d];
    float s1 = sinb[s * HD + d];
    float c2 = cosb[s * HD + d + 64];
    float s2 = sinb[s * HD + d + 64];
    const float* p = x + (long long)s * nh * HD + h * HD;
    __half* po = xo + (long long)s * nh * HD + h * HD;
    float x1 = p[d];
    float x2 = p[d + 64];
    po[d]      = __float2half_rn(x1 * c1 - x2 * s1);
    po[d + 64] = __float2half_rn(x2 * c2 + x1 * s2);
}

// ---------------------------------------------------------------------------
// V transpose: g_v[s][h*128+d] (fp32) -> g_vt[h][d][s] (fp16)
// ---------------------------------------------------------------------------
__global__ void transpose_v(const float* __restrict__ v, __half* __restrict__ vt)
{
    __shared__ float tile[32][33];
    const int h  = blockIdx.z;
    const int s0 = blockIdx.x * 32;
    const int d0 = blockIdx.y * 32;
    const int tx = threadIdx.x, ty = threadIdx.y;
    #pragma unroll
    for (int j = 0; j < 4; j++)
        tile[ty + j * 8][tx] = v[(long long)(s0 + ty + j * 8) * (NKV * HD) + h * HD + d0 + tx];
    __syncthreads();
    #pragma unroll
    for (int j = 0; j < 4; j++)
        vt[(long long)h * HD * S_LEN + (long long)(d0 + ty + j * 8) * S_LEN + s0 + tx] =
            __float2half_rn(tile[tx][ty + j * 8]);
}

// ---------------------------------------------------------------------------
// Causal softmax: fp32 W (checked output) + fp16 Wh (GEMM operand).
// ---------------------------------------------------------------------------
__global__ __launch_bounds__(256) void softmax_causal(float* __restrict__ W,
                                                      __half* __restrict__ Wh)
{
    const int q = blockIdx.x;
    const int h = blockIdx.y;
    const long long off = ((long long)h * S_LEN + q) * S_LEN;
    float* row  = W  + off;
    __half* rowh = Wh + off;
    const int L = q + 1;
    const int tid = threadIdx.x;
    __shared__ float red[32];

    float vals[8];
    int cnt = 0;

    float mx = -3.402823e38f;
    for (int k = tid; k < L; k += 256) {
        float x = row[k];
        vals[cnt++] = x;
        mx = fmaxf(mx, x);
    }
    #pragma unroll
    for (int o = 16; o; o >>= 1) mx = fmaxf(mx, __shfl_xor_sync(0xffffffffu, mx, o));
    if ((tid & 31) == 0) red[tid >> 5] = mx;
    __syncthreads();
    if (tid < 32) {
        float w2 = (tid < 8) ? red[tid] : -3.402823e38f;
        #pragma unroll
        for (int o = 4; o; o >>= 1) w2 = fmaxf(w2, __shfl_xor_sync(0xffffffffu, w2, o));
        if (tid == 0) red[0] = w2;
    }
    __syncthreads();
    mx = red[0];
    __syncthreads();

    float s = 0.f;
    for (int i = 0; i < cnt; i++) {
        float e = expf(vals[i] - mx);
        vals[i] = e;
        s += e;
    }
    #pragma unroll
    for (int o = 16; o; o >>= 1) s += __shfl_xor_sync(0xffffffffu, s, o);
    if ((tid & 31) == 0) red[tid >> 5] = s;
    __syncthreads();
    if (tid < 32) {
        float w2 = (tid < 8) ? red[tid] : 0.f;
        #pragma unroll
        for (int o = 4; o; o >>= 1) w2 += __shfl_xor_sync(0xffffffffu, w2, o);
        if (tid == 0) red[0] = w2;
    }
    __syncthreads();
    const float inv = 1.f / red[0];

    int i = 0;
    for (int k = tid; k < S_LEN; k += 256) {
        float val = (k < L) ? vals[i++] * inv : 0.f;
        row[k]  = val;
        rowh[k] = __float2half_rn(val);
    }
}

// ---------------------------------------------------------------------------
extern "C" void kernel_launch(void* const* d_in, const int* in_sizes, int n_in,
                              void* d_out, int out_size)
{
    const float* hs   = (const float*)d_in[0];
    const float* wq   = (const float*)d_in[1];
    const float* wk   = (const float*)d_in[2];
    const float* wv   = (const float*)d_in[3];
    const float* wo   = (const float*)d_in[4];
    const float* cosb = (const float*)d_in[5];
    const float* sinb = (const float*)d_in[6];
    (void)in_sizes; (void)n_in;

    float* out = (float*)d_out;

    const long long OUT_ELEMS = (long long)S_LEN * NH * HD;
    const long long W_ELEMS   = (long long)NH * S_LEN * S_LEN;

    __half *hsh, *wqh, *wkh, *wvh, *woh, *qh, *kh, *vtp, *aoh, *whp;
    float  *qp, *kp, *vp, *wsc;
    cudaGetSymbolAddress((void**)&hsh, g_hsh);
    cudaGetSymbolAddress((void**)&wqh, g_wqh);
    cudaGetSymbolAddress((void**)&wkh, g_wkh);
    cudaGetSymbolAddress((void**)&wvh, g_wvh);
    cudaGetSymbolAddress((void**)&woh, g_woh);
    cudaGetSymbolAddress((void**)&qp,  g_q);
    cudaGetSymbolAddress((void**)&kp,  g_k);
    cudaGetSymbolAddress((void**)&vp,  g_v);
    cudaGetSymbolAddress((void**)&qh,  g_qh);
    cudaGetSymbolAddress((void**)&kh,  g_kh);
    cudaGetSymbolAddress((void**)&vtp, g_vt);
    cudaGetSymbolAddress((void**)&aoh, g_aoh);
    cudaGetSymbolAddress((void**)&whp, g_wh);
    cudaGetSymbolAddress((void**)&wsc, g_w_scratch);

    float* W = ((long long)out_size >= OUT_ELEMS + W_ELEMS) ? (out + OUT_ELEMS) : wsc;

    // 0) fp16 conversion of inputs
    {
        int n;
        n = S_LEN * HDIM / 4;    cvt_f16<<<(n + 255) / 256, 256>>>((const float4*)hs, (__half2*)hsh, n);
        n = HDIM * HDIM / 4;     cvt_f16<<<(n + 255) / 256, 256>>>((const float4*)wq, (__half2*)wqh, n);
        n = NKV * HD * HDIM / 4; cvt_f16<<<(n + 255) / 256, 256>>>((const float4*)wk, (__half2*)wkh, n);
        n = NKV * HD * HDIM / 4; cvt_f16<<<(n + 255) / 256, 256>>>((const float4*)wv, (__half2*)wvh, n);
        n = HDIM * HDIM / 4;     cvt_f16<<<(n + 255) / 256, 256>>>((const float4*)wo, (__half2*)woh, n);
    }

    // 1) QKV projections: X @ Wx^T -> fp32
    mm_f16<<<dim3(NH * HD / BN,  S_LEN / BM), 512>>>(hsh, wqh, qp,
        HDIM, HDIM, HDIM, NH * HD,  0, 0, 0, 0, 1.f, 0, 0);
    mm_f16<<<dim3(NKV * HD / BN, S_LEN / BM), 512>>>(hsh, wkh, kp,
        HDIM, HDIM, HDIM, NKV * HD, 0, 0, 0, 0, 1.f, 0, 0);
    mm_f16<<<dim3(NKV * HD / BN, S_LEN / BM), 512>>>(hsh, wvh, vp,
        HDIM, HDIM, HDIM, NKV * HD, 0, 0, 0, 0, 1.f, 0, 0);

    // 2) RoPE (fp32 -> fp16 operands)
    rope_kernel<<<(S_LEN * NH  * 64 + 255) / 256, 256>>>(qp, qh, cosb, sinb, NH);
    rope_kernel<<<(S_LEN * NKV * 64 + 255) / 256, 256>>>(kp, kh, cosb, sinb, NKV);

    // 2b) V transpose (fp32 -> fp16)
    transpose_v<<<dim3(S_LEN / 32, HD / 32, NKV), dim3(32, 8)>>>(vp, vtp);

    // 3) Scores: Q_h @ K_{h/4}^T * scaling -> fp32 W, causal block-skip
    mm_f16<<<dim3(S_LEN / BN, S_LEN / BM, NH), 512>>>(qh, kh, W,
        HD, NH * HD, NKV * HD, S_LEN,
        HD, HD, 2, (long long)S_LEN * S_LEN, SCALING, 1, 0);

    // 4) Softmax: W fp32 (checked) + Wh fp16 (operand)
    softmax_causal<<<dim3(S_LEN, NH), 256>>>(W, whp);

    // 5) attn_out = W_h @ (V^T_{h/4})^T, K clipped -> fp16
    mm_f16<<<dim3(1, S_LEN / BM, NH), 512>>>(whp, vtp, aoh,
        S_LEN, S_LEN, S_LEN, NH * HD,
        (long long)S_LEN * S_LEN, (long long)HD * S_LEN, 2, HD, 1.f, 2, 1);

    // 6) out = attn_out @ wo^T -> fp32
    mm_f16<<<dim3(NH * HD / BN, S_LEN / BM), 512>>>(aoh, woh, out,
        HDIM, HDIM, HDIM, NH * HD, 0, 0, 0, 0, 1.f, 0, 0);
}

// round 10
// speedup vs baseline: 2.1469x; 1.1295x over previous
#include <cuda_runtime.h>
#include <cuda_fp16.h>
#include <math.h>
#include <stdint.h>

// ---------------------------------------------------------------------------
// Problem constants: B=1, S=2048, H=4096, NH=32, NKV=8, HD=128
// ---------------------------------------------------------------------------
#define S_LEN 2048
#define HDIM  4096
#define NH    32
#define NKV   8
#define HD    128
#define SCALING 0.08838834764831843f  // 128^-0.5

// Device-global scratch (no runtime allocation allowed)
__device__ __half g_hsh[S_LEN * HDIM];
__device__ __half g_wqh[HDIM * HDIM];
__device__ __half g_wkh[NKV * HD * HDIM];
__device__ __half g_wvh[NKV * HD * HDIM];
__device__ __half g_woh[HDIM * HDIM];
__device__ __half g_qh [S_LEN * NH  * HD];   // fp16 Q post-rope
__device__ __half g_kh [S_LEN * NKV * HD];   // fp16 K post-rope
__device__ __half g_vt [NKV * HD * S_LEN];   // V^T per kv-head, fp16
__device__ __half g_aoh[S_LEN * NH  * HD];   // attn_out fp16
__device__ __half g_wh [(size_t)NH * S_LEN * S_LEN];      // fp16 weights operand
__device__ float  g_w_scratch[(size_t)NH * S_LEN * S_LEN]; // fallback fp32 W

// ---------------------------------------------------------------------------
// Helpers
// ---------------------------------------------------------------------------
__device__ __forceinline__ void mma_f16(float* c, const uint32_t* a,
                                        uint32_t b0, uint32_t b1) {
    asm volatile(
        "mma.sync.aligned.m16n8k16.row.col.f32.f16.f16.f32 "
        "{%0,%1,%2,%3}, {%4,%5,%6,%7}, {%8,%9}, {%0,%1,%2,%3};\n"
        : "+f"(c[0]), "+f"(c[1]), "+f"(c[2]), "+f"(c[3])
        : "r"(a[0]), "r"(a[1]), "r"(a[2]), "r"(a[3]), "r"(b0), "r"(b1));
}
__device__ __forceinline__ void ldsm4(uint32_t* r, uint32_t addr) {
    asm volatile("ldmatrix.sync.aligned.m8n8.x4.shared.b16 {%0,%1,%2,%3}, [%4];"
        : "=r"(r[0]), "=r"(r[1]), "=r"(r[2]), "=r"(r[3]) : "r"(addr));
}
__device__ __forceinline__ void cp16(uint32_t dst, const void* src) {
    asm volatile("cp.async.cg.shared.global [%0], [%1], 16;" :: "r"(dst), "l"(src));
}
#define CP_COMMIT() asm volatile("cp.async.commit_group;")
#define CP_WAIT1()  asm volatile("cp.async.wait_group 1;")
#define CP_WAIT0()  asm volatile("cp.async.wait_group 0;")

#define BM 128
#define BN 128
#define TILE_B 8192        // one 128x32 fp16 tile
#define STAGE_B 16384      // A tile + B tile
#define NSTAGE 3

// ---------------------------------------------------------------------------
// General FP16 GEMM (unchanged mainloop from R7):
//   C[z] = alpha * A[z] @ B[z>>bShift]^T
// A[M,K] k-major fp16 (lda), B[N,K] k-major fp16 (ldb). C fp32 or fp16.
// mode: 0 dense, 1 causal block-skip (bx>by), 2 K clipped to (by+1)*128.
// ---------------------------------------------------------------------------
__global__ __launch_bounds__(512) void mm_f16(
    const __half* __restrict__ A, const __half* __restrict__ B, void* __restrict__ Cv,
    int K, int lda, int ldb, int ldc,
    long long bsA, long long bsB, int bShift, long long bsC,
    float alpha, int mode, int outF16)
{
    const int bx = blockIdx.x, by = blockIdx.y, bz = blockIdx.z;
    if (mode == 1 && bx > by) return;

    A += (long long)bz * bsA;
    B += (long long)(bz >> bShift) * bsB;

    const int Ktot = (mode == 2) ? min(K, (by + 1) * BM) : K;
    const int NT = Ktot >> 5;

    __shared__ __align__(128) char smem[NSTAGE * STAGE_B];
    const uint32_t sb0 = (uint32_t)__cvta_generic_to_shared(smem);

    const int tid  = threadIdx.x;
    const int lane = tid & 31;
    const int w    = tid >> 5;
    const int wm   = w >> 2;
    const int wn   = w & 3;
    const int t4   = lane >> 2;
    const int l4   = lane & 3;

    const int rr = tid >> 2;
    const int cc = tid & 3;
    const uint32_t offT = (uint32_t)(rr * 64 + ((cc ^ ((rr >> 1) & 3)) << 4));
    const __half* gA = A + (long long)(by * BM + rr) * lda + cc * 8;
    const __half* gB = B + (long long)(bx * BN + rr) * ldb + cc * 8;

    uint32_t aoff[2], boff[2];
    {
        const int ra = wm * 32 + (lane & 15);
        const int rb = wn * 32 + (lane & 15);
        #pragma unroll
        for (int ks = 0; ks < 2; ks++) {
            const int cha = ks * 2 + (lane >> 4);
            aoff[ks] = (uint32_t)(ra * 64 + ((cha ^ ((ra >> 1) & 3)) << 4));
            boff[ks] = (uint32_t)(TILE_B + rb * 64 + ((cha ^ ((rb >> 1) & 3)) << 4));
        }
    }

    float acc[2][4][4];
    #pragma unroll
    for (int i = 0; i < 2; i++)
        #pragma unroll
        for (int j = 0; j < 4; j++)
            #pragma unroll
            for (int r = 0; r < 4; r++) acc[i][j][r] = 0.f;

    #pragma unroll
    for (int s = 0; s < 2; s++) {
        if (s < NT) {
            const uint32_t d = sb0 + s * STAGE_B + offT;
            cp16(d,          gA + s * 32);
            cp16(d + TILE_B, gB + s * 32);
        }
        CP_COMMIT();
    }

    for (int t = 0; t < NT; t++) {
        CP_WAIT1();
        __syncthreads();
        const uint32_t sb = sb0 + (t % NSTAGE) * STAGE_B;

        #pragma unroll
        for (int ks = 0; ks < 2; ks++) {
            uint32_t a[2][4], b[2][4];
            #pragma unroll
            for (int mi = 0; mi < 2; mi++) ldsm4(a[mi], sb + aoff[ks] + mi * 1024);
            #pragma unroll
            for (int p = 0; p < 2; p++)    ldsm4(b[p],  sb + boff[ks] + p * 1024);
            #pragma unroll
            for (int mi = 0; mi < 2; mi++)
                #pragma unroll
                for (int p = 0; p < 2; p++) {
                    mma_f16(acc[mi][p * 2 + 0], a[mi], b[p][0], b[p][2]);
                    mma_f16(acc[mi][p * 2 + 1], a[mi], b[p][1], b[p][3]);
                }
        }

        const int tn = t + 2;
        if (tn < NT) {
            const uint32_t d = sb0 + (tn % NSTAGE) * STAGE_B + offT;
            cp16(d,          gA + tn * 32);
            cp16(d + TILE_B, gB + tn * 32);
        }
        CP_COMMIT();
    }

    #pragma unroll
    for (int mi = 0; mi < 2; mi++) {
        const int r0 = by * BM + wm * 32 + mi * 16 + t4;
        #pragma unroll
        for (int ni = 0; ni < 4; ni++) {
            const int c0 = bx * BN + wn * 32 + ni * 8 + 2 * l4;
            float v0 = acc[mi][ni][0] * alpha, v1 = acc[mi][ni][1] * alpha;
            float v2 = acc[mi][ni][2] * alpha, v3 = acc[mi][ni][3] * alpha;
            if (outF16) {
                __half* C = (__half*)Cv + (long long)bz * bsC;
                *reinterpret_cast<__half2*>(&C[(long long)r0 * ldc + c0]) =
                    __floats2half2_rn(v0, v1);
                *reinterpret_cast<__half2*>(&C[(long long)(r0 + 8) * ldc + c0]) =
                    __floats2half2_rn(v2, v3);
            } else {
                float* C = (float*)Cv + (long long)bz * bsC;
                *reinterpret_cast<float2*>(&C[(long long)r0 * ldc + c0]) = make_float2(v0, v1);
                *reinterpret_cast<float2*>(&C[(long long)(r0 + 8) * ldc + c0]) = make_float2(v2, v3);
            }
        }
    }
}

// ---------------------------------------------------------------------------
// Merged QKV projection + RoPE + V-transpose.
// grid (48, 16): bx<32 -> Q head bx (rope), bx<40 -> K head bx-32 (rope),
// else V head bx-40 (transpose). A = hs fp16, B = per-class weight, K=4096.
// RoPE arithmetic in fp32 (identical to unfused path); staging via a
// conflict-free [64][132] fp32 smem overlay on the (drained) stage buffer.
// ---------------------------------------------------------------------------
__global__ __launch_bounds__(512) void qkv_rope(
    const __half* __restrict__ hsA,
    const __half* __restrict__ wq, const __half* __restrict__ wk,
    const __half* __restrict__ wv,
    __half* __restrict__ qh, __half* __restrict__ kh, __half* __restrict__ vt,
    const float* __restrict__ cosb, const float* __restrict__ sinb)
{
    const int bx = blockIdx.x, by = blockIdx.y;

    const __half* Bw; int h; int epi;  // 0 rope-Q, 1 rope-K, 2 trans-V
    if (bx < 32)      { Bw = wq; h = bx;      epi = 0; }
    else if (bx < 40) { Bw = wk; h = bx - 32; epi = 1; }
    else              { Bw = wv; h = bx - 40; epi = 2; }

    __shared__ __align__(128) char smem[NSTAGE * STAGE_B];
    const uint32_t sb0 = (uint32_t)__cvta_generic_to_shared(smem);
    float* smT = reinterpret_cast<float*>(smem);   // [64][132] overlay (post-drain)

    const int tid  = threadIdx.x;
    const int lane = tid & 31;
    const int w    = tid >> 5;
    const int wm   = w >> 2;
    const int wn   = w & 3;
    const int t4   = lane >> 2;
    const int l4   = lane & 3;

    const int rr = tid >> 2;
    const int cc = tid & 3;
    const uint32_t offT = (uint32_t)(rr * 64 + ((cc ^ ((rr >> 1) & 3)) << 4));
    const __half* gA = hsA + (long long)(by * BM + rr) * HDIM + cc * 8;
    const __half* gB = Bw  + (long long)(h  * BN + rr) * HDIM + cc * 8;

    uint32_t aoff[2], boff[2];
    {
        const int ra = wm * 32 + (lane & 15);
        const int rb = wn * 32 + (lane & 15);
        #pragma unroll
        for (int ks = 0; ks < 2; ks++) {
            const int cha = ks * 2 + (lane >> 4);
        aoff[ks] = (uint32_t)(ra * 64 + ((cha ^ ((ra >> 1) & 3)) << 4));
        boff[ks] = (uint32_t)(TILE_B + rb * 64 + ((cha ^ ((rb >> 1) & 3)) << 4));
        }
    }

    float acc[2][4][4];
    #pragma unroll
    for (int i = 0; i < 2; i++)
        #pragma unroll
        for (int j = 0; j < 4; j++)
            #pragma unroll
            for (int r = 0; r < 4; r++) acc[i][j][r] = 0.f;

    const int NT = HDIM >> 5;   // 128

    #pragma unroll
    for (int s = 0; s < 2; s++) {
        const uint32_t d = sb0 + s * STAGE_B + offT;
        cp16(d,          gA + s * 32);
        cp16(d + TILE_B, gB + s * 32);
        CP_COMMIT();
    }

    for (int t = 0; t < NT; t++) {
        CP_WAIT1();
        __syncthreads();
        const uint32_t sb = sb0 + (t % NSTAGE) * STAGE_B;

        #pragma unroll
        for (int ks = 0; ks < 2; ks++) {
            uint32_t a[2][4], b[2][4];
            #pragma unroll
            for (int mi = 0; mi < 2; mi++) ldsm4(a[mi], sb + aoff[ks] + mi * 1024);
            #pragma unroll
            for (int p = 0; p < 2; p++)    ldsm4(b[p],  sb + boff[ks] + p * 1024);
            #pragma unroll
            for (int mi = 0; mi < 2; mi++)
                #pragma unroll
                for (int p = 0; p < 2; p++) {
                    mma_f16(acc[mi][p * 2 + 0], a[mi], b[p][0], b[p][2]);
                    mma_f16(acc[mi][p * 2 + 1], a[mi], b[p][1], b[p][3]);
                }
        }

        const int tn = t + 2;
        if (tn < NT) {
            const uint32_t d = sb0 + (tn % NSTAGE) * STAGE_B + offT;
            cp16(d,          gA + tn * 32);
            cp16(d + TILE_B, gB + tn * 32);
        }
        CP_COMMIT();
    }

    // Drain async copies fully, then the stage buffer becomes the smT overlay.
    CP_WAIT0();
    __syncthreads();

    if (epi < 2) {
        // ---- RoPE epilogue ----
        const int nh = (epi == 0) ? NH : NKV;
        __half* outp = (epi == 0) ? qh : kh;
        // Warps holding cols 64..127 stage x2 = proj[:, 64..127] into smT[d2][r]
        if (wn >= 2) {
            #pragma unroll
            for (int mi = 0; mi < 2; mi++)
                #pragma unroll
                for (int ni = 0; ni < 4; ni++) {
                    const int d2 = (wn - 2) * 32 + ni * 8 + 2 * l4;
                    #pragma unroll
                    for (int p = 0; p < 2; p++) {
                        const int r = wm * 32 + mi * 16 + t4 + p * 8;
                        smT[d2 * 132 + r]       = acc[mi][ni][p * 2 + 0];
                        smT[(d2 + 1) * 132 + r] = acc[mi][ni][p * 2 + 1];
                    }
                }
        }
        __syncthreads();
        // Warps holding cols 0..63 compute both rope halves and write fp16.
        if (wn < 2) {
            #pragma unroll
            for (int mi = 0; mi < 2; mi++)
                #pragma unroll
                for (int ni = 0; ni < 4; ni++) {
                    const int d = wn * 32 + ni * 8 + 2 * l4;   // 0..63, even
                    #pragma unroll
                    for (int p = 0; p < 2; p++) {
                        const int r = wm * 32 + mi * 16 + t4 + p * 8;
                        const int s = by * 128 + r;
                        const float x1a = acc[mi][ni][p * 2 + 0];
                        const float x1b = acc[mi][ni][p * 2 + 1];
                        const float x2a = smT[d * 132 + r];
                        const float x2b = smT[(d + 1) * 132 + r];
                        const float2 cl = *(const float2*)(cosb + (size_t)s * HD + d);
                        const float2 sl = *(const float2*)(sinb + (size_t)s * HD + d);
                        const float2 chh = *(const float2*)(cosb + (size_t)s * HD + d + 64);
                        const float2 shh = *(const float2*)(sinb + (size_t)s * HD + d + 64);
                        __half2 lo = __floats2half2_rn(x1a * cl.x - x2a * sl.x,
                                                       x1b * cl.y - x2b * sl.y);
                        __half2 hi = __floats2half2_rn(x2a * chh.x + x1a * shh.x,
                                                       x2b * chh.y + x1b * shh.y);
                        __half* o = outp + (size_t)s * nh * HD + h * HD + d;
                        *reinterpret_cast<__half2*>(o)      = lo;
                        *reinterpret_cast<__half2*>(o + 64) = hi;
                    }
                }
        }
    } else {
        // ---- V transpose epilogue: vt[h][d][s] = proj[s][d] ----
        #pragma unroll
        for (int pass = 0; pass < 2; pass++) {
            const bool writer = (pass == 0) ? (wn < 2) : (wn >= 2);
            if (writer) {
                #pragma unroll
                for (int mi = 0; mi < 2; mi++)
                    #pragma unroll
                    for (int ni = 0; ni < 4; ni++) {
                        const int dl = (wn - 2 * pass) * 32 + ni * 8 + 2 * l4; // 0..63
                        #pragma unroll
                        for (int p = 0; p < 2; p++) {
                            const int r = wm * 32 + mi * 16 + t4 + p * 8;
                            smT[dl * 132 + r]       = acc[mi][ni][p * 2 + 0];
                            smT[(dl + 1) * 132 + r] = acc[mi][ni][p * 2 + 1];
                        }
                    }
            }
            __syncthreads();
            #pragma unroll 4
            for (int l = 0; l < 16; l++) {
                const int e  = l * 512 + tid;
                const int dl = e >> 7;
                const int sl = e & 127;
                vt[(size_t)h * HD * S_LEN + (size_t)(dl + pass * 64) * S_LEN
                   + by * 128 + sl] = __float2half_rn(smT[dl * 132 + sl]);
            }
            __syncthreads();
        }
    }
}

// ---------------------------------------------------------------------------
// fp32 -> fp16 conversion (rne); 2 coalesced float4 per thread.
// ---------------------------------------------------------------------------
__global__ void cvt_f16(const float4* __restrict__ in, __half2* __restrict__ out, int n4)
{
    const int half = n4 >> 1;
    const int i = blockIdx.x * blockDim.x + threadIdx.x;
    if (i < half) {
        float4 v = in[i];
        out[i * 2 + 0] = __floats2half2_rn(v.x, v.y);
        out[i * 2 + 1] = __floats2half2_rn(v.z, v.w);
        float4 u = in[i + half];
        out[(i + half) * 2 + 0] = __floats2half2_rn(u.x, u.y);
        out[(i + half) * 2 + 1] = __floats2half2_rn(u.z, u.w);
    }
}

// ---------------------------------------------------------------------------
// Causal softmax, float4 IO: fp32 W (checked) + fp16 Wh (operand, clipped to
// the 128-block containing q — attn@V never reads beyond).
// ---------------------------------------------------------------------------
__global__ __launch_bounds__(256) void softmax_causal(float* __restrict__ W,
                                                      __half* __restrict__ Wh)
{
    const int q = blockIdx.x;
    const int h = blockIdx.y;
    const long long off = ((long long)h * S_LEN + q) * S_LEN;
    float4* row4  = reinterpret_cast<float4*>(W + off);
    __half2* rowh2 = reinterpret_cast<__half2*>(Wh + off);
    const int L = q + 1;
    const int clip4 = (((q >> 7) + 1) << 7) >> 2;   // Wh write bound in vectors
    const int tid = threadIdx.x;
    __shared__ float red[32];

    float4 va[2];
    const float NEGINF = -3.402823e38f;

    // --- load + masked max ---
    float mx = NEGINF;
    #pragma unroll
    for (int j = 0; j < 2; j++) {
        const int iv = tid + j * 256;
        const int k0 = iv * 4;
        if (k0 < L) {
            float4 v = row4[iv];
            va[j] = v;
            mx = fmaxf(mx, v.x);
            if (k0 + 1 < L) mx = fmaxf(mx, v.y);
            if (k0 + 2 < L) mx = fmaxf(mx, v.z);
            if (k0 + 3 < L) mx = fmaxf(mx, v.w);
        }
    }
    #pragma unroll
    for (int o = 16; o; o >>= 1) mx = fmaxf(mx, __shfl_xor_sync(0xffffffffu, mx, o));
    if ((tid & 31) == 0) red[tid >> 5] = mx;
    __syncthreads();
    if (tid < 32) {
        float w2 = (tid < 8) ? red[tid] : NEGINF;
        #pragma unroll
        for (int o = 4; o; o >>= 1) w2 = fmaxf(w2, __shfl_xor_sync(0xffffffffu, w2, o));
        if (tid == 0) red[0] = w2;
    }
    __syncthreads();
    mx = red[0];
    __syncthreads();

    // --- exp + sum (masked; exps kept in registers) ---
    float s = 0.f;
    #pragma unroll
    for (int j = 0; j < 2; j++) {
        const int iv = tid + j * 256;
        const int k0 = iv * 4;
        float4 e = make_float4(0.f, 0.f, 0.f, 0.f);
        if (k0 < L) {
            e.x = expf(va[j].x - mx);
            if (k0 + 1 < L) e.y = expf(va[j].y - mx);
            if (k0 + 2 < L) e.z = expf(va[j].z - mx);
            if (k0 + 3 < L) e.w = expf(va[j].w - mx);
            s += e.x + e.y + e.z + e.w;
        }
        va[j] = e;
    }
    #pragma unroll
    for (int o = 16; o; o >>= 1) s += __shfl_xor_sync(0xffffffffu, s, o);
    if ((tid & 31) == 0) red[tid >> 5] = s;
    __syncthreads();
    if (tid < 32) {
        float w2 = (tid < 8) ? red[tid] : 0.f;
        #pragma unroll
        for (int o = 4; o; o >>= 1) w2 += __shfl_xor_sync(0xffffffffu, w2, o);
        if (tid == 0) red[0] = w2;
    }
    __syncthreads();
    const float inv = 1.f / red[0];

    // --- write normalized W (full row) + clipped Wh ---
    #pragma unroll
    for (int j = 0; j < 2; j++) {
        const int iv = tid + j * 256;
        float4 o4 = make_float4(va[j].x * inv, va[j].y * inv,
                                va[j].z * inv, va[j].w * inv);
        row4[iv] = o4;
        if (iv < clip4) {
            rowh2[iv * 2 + 0] = __floats2half2_rn(o4.x, o4.y);
            rowh2[iv * 2 + 1] = __floats2half2_rn(o4.z, o4.w);
        }
    }
}

// ---------------------------------------------------------------------------
extern "C" void kernel_launch(void* const* d_in, const int* in_sizes, int n_in,
                              void* d_out, int out_size)
{
    const float* hs   = (const float*)d_in[0];
    const float* wq   = (const float*)d_in[1];
    const float* wk   = (const float*)d_in[2];
    const float* wv   = (const float*)d_in[3];
    const float* wo   = (const float*)d_in[4];
    const float* cosb = (const float*)d_in[5];
    const float* sinb = (const float*)d_in[6];
    (void)in_sizes; (void)n_in;

    float* out = (float*)d_out;

    const long long OUT_ELEMS = (long long)S_LEN * NH * HD;
    const long long W_ELEMS   = (long long)NH * S_LEN * S_LEN;

    __half *hsh, *wqh, *wkh, *wvh, *woh, *qh, *kh, *vtp, *aoh, *whp;
    float  *wsc;
    cudaGetSymbolAddress((void**)&hsh, g_hsh);
    cudaGetSymbolAddress((void**)&wqh, g_wqh);
    cudaGetSymbolAddress((void**)&wkh, g_wkh);
    cudaGetSymbolAddress((void**)&wvh, g_wvh);
    cudaGetSymbolAddress((void**)&woh, g_woh);
    cudaGetSymbolAddress((void**)&qh,  g_qh);
    cudaGetSymbolAddress((void**)&kh,  g_kh);
    cudaGetSymbolAddress((void**)&vtp, g_vt);
    cudaGetSymbolAddress((void**)&aoh, g_aoh);
    cudaGetSymbolAddress((void**)&whp, g_wh);
    cudaGetSymbolAddress((void**)&wsc, g_w_scratch);

    float* W = ((long long)out_size >= OUT_ELEMS + W_ELEMS) ? (out + OUT_ELEMS) : wsc;

    // 0) fp16 conversion of inputs
    {
        int n;
        n = S_LEN * HDIM / 4;    cvt_f16<<<(n / 2 + 255) / 256, 256>>>((const float4*)hs, (__half2*)hsh, n);
        n = HDIM * HDIM / 4;     cvt_f16<<<(n / 2 + 255) / 256, 256>>>((const float4*)wq, (__half2*)wqh, n);
        n = NKV * HD * HDIM / 4; cvt_f16<<<(n / 2 + 255) / 256, 256>>>((const float4*)wk, (__half2*)wkh, n);
        n = NKV * HD * HDIM / 4; cvt_f16<<<(n / 2 + 255) / 256, 256>>>((const float4*)wv, (__half2*)wvh, n);
        n = HDIM * HDIM / 4;     cvt_f16<<<(n / 2 + 255) / 256, 256>>>((const float4*)wo, (__half2*)woh, n);
    }

    // 1) Merged QKV projections + RoPE + V-transpose
    qkv_rope<<<dim3(48, S_LEN / BM), 512>>>(hsh, wqh, wkh, wvh,
                                            qh, kh, vtp, cosb, sinb);

    // 2) Scores: Q_h @ K_{h/4}^T * scaling -> fp32 W, causal block-skip
    mm_f16<<<dim3(S_LEN / BN, S_LEN / BM, NH), 512>>>(qh, kh, W,
        HD, NH * HD, NKV * HD, S_LEN,
        HD, HD, 2, (long long)S_LEN * S_LEN, SCALING, 1, 0);

    // 3) Softmax: W fp32 (checked) + Wh fp16 (operand, clipped)
    softmax_causal<<<dim3(S_LEN, NH), 256>>>(W, whp);

    // 4) attn_out = W_h @ (V^T_{h/4})^T, K clipped -> fp16
    mm_f16<<<dim3(1, S_LEN / BM, NH), 512>>>(whp, vtp, aoh,
        S_LEN, S_LEN, S_LEN, NH * HD,
        (long long)S_LEN * S_LEN, (long long)HD * S_LEN, 2, HD, 1.f, 2, 1);

    // 5) out = attn_out @ wo^T -> fp32
    mm_f16<<<dim3(NH * HD / BN, S_LEN / BM), 512>>>(aoh, woh, out,
        HDIM, HDIM, HDIM, NH * HD, 0, 0, 0, 0, 1.f, 0, 0);
}

// round 11
// speedup vs baseline: 2.3033x; 1.0728x over previous
#include <cuda_runtime.h>
#include <cuda_fp16.h>
#include <math.h>
#include <stdint.h>

// ---------------------------------------------------------------------------
// Problem constants: B=1, S=2048, H=4096, NH=32, NKV=8, HD=128
// ---------------------------------------------------------------------------
#define S_LEN 2048
#define HDIM  4096
#define NH    32
#define NKV   8
#define HD    128
#define SCALING 0.08838834764831843f  // 128^-0.5

// Device-global scratch (no runtime allocation allowed)
__device__ __half g_hsh[S_LEN * HDIM];
__device__ __half g_wqh[HDIM * HDIM];
__device__ __half g_wkh[NKV * HD * HDIM];
__device__ __half g_wvh[NKV * HD * HDIM];
__device__ __half g_woh[HDIM * HDIM];
__device__ __half g_qh [S_LEN * NH  * HD];   // fp16 Q post-rope
__device__ __half g_kh [S_LEN * NKV * HD];   // fp16 K post-rope
__device__ __half g_vt [NKV * HD * S_LEN];   // V^T per kv-head, fp16
__device__ __half g_aoh[S_LEN * NH  * HD];   // attn_out fp16
__device__ __half g_wh [(size_t)NH * S_LEN * S_LEN];      // fp16 weights operand
__device__ float  g_w_scratch[(size_t)NH * S_LEN * S_LEN]; // fallback fp32 W

// ---------------------------------------------------------------------------
// Helpers
// ---------------------------------------------------------------------------
__device__ __forceinline__ void mma_f16(float* c, const uint32_t* a,
                                        uint32_t b0, uint32_t b1) {
    asm volatile(
        "mma.sync.aligned.m16n8k16.row.col.f32.f16.f16.f32 "
        "{%0,%1,%2,%3}, {%4,%5,%6,%7}, {%8,%9}, {%0,%1,%2,%3};\n"
        : "+f"(c[0]), "+f"(c[1]), "+f"(c[2]), "+f"(c[3])
        : "r"(a[0]), "r"(a[1]), "r"(a[2]), "r"(a[3]), "r"(b0), "r"(b1));
}
__device__ __forceinline__ void ldsm4(uint32_t* r, uint32_t addr) {
    asm volatile("ldmatrix.sync.aligned.m8n8.x4.shared.b16 {%0,%1,%2,%3}, [%4];"
        : "=r"(r[0]), "=r"(r[1]), "=r"(r[2]), "=r"(r[3]) : "r"(addr));
}
__device__ __forceinline__ void cp16(uint32_t dst, const void* src) {
    asm volatile("cp.async.cg.shared.global [%0], [%1], 16;" :: "r"(dst), "l"(src));
}
#define CP_COMMIT() asm volatile("cp.async.commit_group;")
#define CP_WAIT1()  asm volatile("cp.async.wait_group 1;")
#define CP_WAIT0()  asm volatile("cp.async.wait_group 0;")

// Tile geometry: CTA 128x128, K-chunk 64 (128B fp16 rows, Swizzle<3,3,3>).
#define BM 128
#define BN 128
#define TILE_B 16384       // one 128x64 fp16 tile (128 rows x 128B)
#define STAGE_B 32768      // A tile + B tile
#define NSTAGE 3
#define DYN_SMEM (NSTAGE * STAGE_B)   // 98304

// ---------------------------------------------------------------------------
// General FP16 GEMM:  C[z] = alpha * A[z] @ B[z>>bShift]^T
// A[M,K] k-major fp16 (lda), B[N,K] k-major fp16 (ldb). C fp32 or fp16.
// 512 threads, 16 warps (4x4), warp tile 32x32.
// mode: 0 dense, 1 causal (skip bx>by; those CTAs zero-fill their C tile),
//       2 K clipped to (by+1)*128.
// Smem: 16B chunk c of row r at byte r*128 + ((c ^ (r&7))<<4).
// ---------------------------------------------------------------------------
__global__ __launch_bounds__(512) void mm_f16(
    const __half* __restrict__ A, const __half* __restrict__ B, void* __restrict__ Cv,
    int K, int lda, int ldb, int ldc,
    long long bsA, long long bsB, int bShift, long long bsC,
    float alpha, int mode, int outF16)
{
    const int bx = blockIdx.x, by = blockIdx.y, bz = blockIdx.z;
    const int tid  = threadIdx.x;

    if (mode == 1 && bx > by) {
        // Zero-fill this upper-triangle C tile (fp32) and exit.
        float* C = (float*)Cv + (long long)bz * bsC;
        const float4 z = make_float4(0.f, 0.f, 0.f, 0.f);
        #pragma unroll 4
        for (int i = tid; i < 128 * 32; i += 512) {
            const int r = i >> 5, c = (i & 31) << 2;
            *reinterpret_cast<float4*>(&C[(long long)(by * BM + r) * ldc + bx * BN + c]) = z;
        }
        return;
    }

    A += (long long)bz * bsA;
    B += (long long)(bz >> bShift) * bsB;

    const int Ktot = (mode == 2) ? min(K, (by + 1) * BM) : K;
    const int NT = Ktot >> 6;    // K-chunks of 64

    extern __shared__ __align__(128) char smem[];
    const uint32_t sb0 = (uint32_t)__cvta_generic_to_shared(smem);

    const int lane = tid & 31;
    const int w    = tid >> 5;
    const int wm   = w >> 2;
    const int wn   = w & 3;
    const int t4   = lane >> 2;
    const int l4   = lane & 3;

    // Loader: thread covers row rr, chunks cc and cc+4 of each tile.
    const int rr = tid >> 2;
    const int cc = tid & 3;
    const uint32_t offA0 = (uint32_t)(rr * 128 + (((cc    ) ^ (rr & 7)) << 4));
    const uint32_t offA1 = (uint32_t)(rr * 128 + (((cc + 4) ^ (rr & 7)) << 4));
    const __half* gA = A + (long long)(by * BM + rr) * lda + cc * 8;
    const __half* gB = B + (long long)(bx * BN + rr) * ldb + cc * 8;

    // ldmatrix per-lane byte offsets (within stage) for ksteps 0..3.
    uint32_t aoff[4], boff[4];
    {
        const int ra = wm * 32 + (lane & 15);
        const int rb = wn * 32 + (lane & 15);
        #pragma unroll
        for (int ks = 0; ks < 4; ks++) {
            const int cha = ks * 2 + (lane >> 4);
            aoff[ks] = (uint32_t)(ra * 128 + ((cha ^ (ra & 7)) << 4));
            boff[ks] = (uint32_t)(TILE_B + rb * 128 + ((cha ^ (rb & 7)) << 4));
        }
    }

    float acc[2][4][4];
    #pragma unroll
    for (int i = 0; i < 2; i++)
        #pragma unroll
        for (int j = 0; j < 4; j++)
            #pragma unroll
            for (int r = 0; r < 4; r++) acc[i][j][r] = 0.f;

    #pragma unroll
    for (int s = 0; s < 2; s++) {
        if (s < NT) {
            const uint32_t d = sb0 + s * STAGE_B;
            const __half* a0 = gA + s * 64;
            const __half* b0 = gB + s * 64;
            cp16(d + offA0,          a0);
            cp16(d + offA1,          a0 + 32);
            cp16(d + TILE_B + offA0, b0);
            cp16(d + TILE_B + offA1, b0 + 32);
        }
        CP_COMMIT();
    }

    for (int t = 0; t < NT; t++) {
        CP_WAIT1();
        __syncthreads();
        const uint32_t sb = sb0 + (t % NSTAGE) * STAGE_B;

        #pragma unroll
        for (int ks = 0; ks < 4; ks++) {
            uint32_t a[2][4], b[2][4];
            #pragma unroll
            for (int mi = 0; mi < 2; mi++) ldsm4(a[mi], sb + aoff[ks] + mi * 2048);
            #pragma unroll
            for (int p = 0; p < 2; p++)    ldsm4(b[p],  sb + boff[ks] + p * 2048);
            #pragma unroll
            for (int mi = 0; mi < 2; mi++)
                #pragma unroll
                for (int p = 0; p < 2; p++) {
                    mma_f16(acc[mi][p * 2 + 0], a[mi], b[p][0], b[p][2]);
                    mma_f16(acc[mi][p * 2 + 1], a[mi], b[p][1], b[p][3]);
                }
        }

        const int tn = t + 2;
        if (tn < NT) {
            const uint32_t d = sb0 + (tn % NSTAGE) * STAGE_B;
            const __half* a0 = gA + tn * 64;
            const __half* b0 = gB + tn * 64;
            cp16(d + offA0,          a0);
            cp16(d + offA1,          a0 + 32);
            cp16(d + TILE_B + offA0, b0);
            cp16(d + TILE_B + offA1, b0 + 32);
        }
        CP_COMMIT();
    }

    #pragma unroll
    for (int mi = 0; mi < 2; mi++) {
        const int r0 = by * BM + wm * 32 + mi * 16 + t4;
        #pragma unroll
        for (int ni = 0; ni < 4; ni++) {
            const int c0 = bx * BN + wn * 32 + ni * 8 + 2 * l4;
            float v0 = acc[mi][ni][0] * alpha, v1 = acc[mi][ni][1] * alpha;
            float v2 = acc[mi][ni][2] * alpha, v3 = acc[mi][ni][3] * alpha;
            if (outF16) {
                __half* C = (__half*)Cv + (long long)bz * bsC;
                *reinterpret_cast<__half2*>(&C[(long long)r0 * ldc + c0]) =
                    __floats2half2_rn(v0, v1);
                *reinterpret_cast<__half2*>(&C[(long long)(r0 + 8) * ldc + c0]) =
                    __floats2half2_rn(v2, v3);
            } else {
                float* C = (float*)Cv + (long long)bz * bsC;
                *reinterpret_cast<float2*>(&C[(long long)r0 * ldc + c0]) = make_float2(v0, v1);
                *reinterpret_cast<float2*>(&C[(long long)(r0 + 8) * ldc + c0]) = make_float2(v2, v3);
            }
        }
    }
}

// ---------------------------------------------------------------------------
// Merged QKV projection + RoPE + V-transpose (BK=64 mainloop).
// grid (48, 16): bx<32 -> Q head bx (rope), bx<40 -> K head bx-32 (rope),
// else V head bx-40 (transpose).
// ---------------------------------------------------------------------------
__global__ __launch_bounds__(512) void qkv_rope(
    const __half* __restrict__ hsA,
    const __half* __restrict__ wq, const __half* __restrict__ wk,
    const __half* __restrict__ wv,
    __half* __restrict__ qh, __half* __restrict__ kh, __half* __restrict__ vt,
    const float* __restrict__ cosb, const float* __restrict__ sinb)
{
    const int bx = blockIdx.x, by = blockIdx.y;

    const __half* Bw; int h; int epi;  // 0 rope-Q, 1 rope-K, 2 trans-V
    if (bx < 32)      { Bw = wq; h = bx;      epi = 0; }
    else if (bx < 40) { Bw = wk; h = bx - 32; epi = 1; }
    else              { Bw = wv; h = bx - 40; epi = 2; }

    extern __shared__ __align__(128) char smem[];
    const uint32_t sb0 = (uint32_t)__cvta_generic_to_shared(smem);
    float* smT = reinterpret_cast<float*>(smem);   // [64][132] overlay (post-drain)

    const int tid  = threadIdx.x;
    const int lane = tid & 31;
    const int w    = tid >> 5;
    const int wm   = w >> 2;
    const int wn   = w & 3;
    const int t4   = lane >> 2;
    const int l4   = lane & 3;

    const int rr = tid >> 2;
    const int cc = tid & 3;
    const uint32_t offA0 = (uint32_t)(rr * 128 + (((cc    ) ^ (rr & 7)) << 4));
    const uint32_t offA1 = (uint32_t)(rr * 128 + (((cc + 4) ^ (rr & 7)) << 4));
    const __half* gA = hsA + (long long)(by * BM + rr) * HDIM + cc * 8;
    const __half* gB = Bw  + (long long)(h  * BN + rr) * HDIM + cc * 8;

    uint32_t aoff[4], boff[4];
    {
        const int ra = wm * 32 + (lane & 15);
        const int rb = wn * 32 + (lane & 15);
        #pragma unroll
        for (int ks = 0; ks < 4; ks++) {
            const int cha = ks * 2 + (lane >> 4);
            aoff[ks] = (uint32_t)(ra * 128 + ((cha ^ (ra & 7)) << 4));
            boff[ks] = (uint32_t)(TILE_B + rb * 128 + ((cha ^ (rb & 7)) << 4));
        }
    }

    float acc[2][4][4];
    #pragma unroll
    for (int i = 0; i < 2; i++)
        #pragma unroll
        for (int j = 0; j < 4; j++)
            #pragma unroll
            for (int r = 0; r < 4; r++) acc[i][j][r] = 0.f;

    const int NT = HDIM >> 6;   // 64

    #pragma unroll
    for (int s = 0; s < 2; s++) {
        const uint32_t d = sb0 + s * STAGE_B;
        const __half* a0 = gA + s * 64;
        const __half* b0 = gB + s * 64;
        cp16(d + offA0,          a0);
        cp16(d + offA1,          a0 + 32);
        cp16(d + TILE_B + offA0, b0);
        cp16(d + TILE_B + offA1, b0 + 32);
        CP_COMMIT();
    }

    for (int t = 0; t < NT; t++) {
        CP_WAIT1();
        __syncthreads();
        const uint32_t sb = sb0 + (t % NSTAGE) * STAGE_B;

        #pragma unroll
        for (int ks = 0; ks < 4; ks++) {
            uint32_t a[2][4], b[2][4];
            #pragma unroll
            for (int mi = 0; mi < 2; mi++) ldsm4(a[mi], sb + aoff[ks] + mi * 2048);
            #pragma unroll
            for (int p = 0; p < 2; p++)    ldsm4(b[p],  sb + boff[ks] + p * 2048);
            #pragma unroll
            for (int mi = 0; mi < 2; mi++)
                #pragma unroll
                for (int p = 0; p < 2; p++) {
                    mma_f16(acc[mi][p * 2 + 0], a[mi], b[p][0], b[p][2]);
                    mma_f16(acc[mi][p * 2 + 1], a[mi], b[p][1], b[p][3]);
                }
        }

        const int tn = t + 2;
        if (tn < NT) {
            const uint32_t d = sb0 + (tn % NSTAGE) * STAGE_B;
            const __half* a0 = gA + tn * 64;
            const __half* b0 = gB + tn * 64;
            cp16(d + offA0,          a0);
            cp16(d + offA1,          a0 + 32);
            cp16(d + TILE_B + offA0, b0);
            cp16(d + TILE_B + offA1, b0 + 32);
        }
        CP_COMMIT();
    }

    // Drain async copies fully; stage buffer becomes the smT overlay.
    CP_WAIT0();
    __syncthreads();

    if (epi < 2) {
        // ---- RoPE epilogue ----
        const int nh = (epi == 0) ? NH : NKV;
        __half* outp = (epi == 0) ? qh : kh;
        if (wn >= 2) {
            #pragma unroll
            for (int mi = 0; mi < 2; mi++)
                #pragma unroll
                for (int ni = 0; ni < 4; ni++) {
                    const int d2 = (wn - 2) * 32 + ni * 8 + 2 * l4;
                    #pragma unroll
                    for (int p = 0; p < 2; p++) {
                        const int r = wm * 32 + mi * 16 + t4 + p * 8;
                        smT[d2 * 132 + r]       = acc[mi][ni][p * 2 + 0];
                        smT[(d2 + 1) * 132 + r] = acc[mi][ni][p * 2 + 1];
                    }
                }
        }
        __syncthreads();
        if (wn < 2) {
            #pragma unroll
            for (int mi = 0; mi < 2; mi++)
                #pragma unroll
                for (int ni = 0; ni < 4; ni++) {
                    const int d = wn * 32 + ni * 8 + 2 * l4;   // 0..63, even
                    #pragma unroll
                    for (int p = 0; p < 2; p++) {
                        const int r = wm * 32 + mi * 16 + t4 + p * 8;
                        const int s = by * 128 + r;
                        const float x1a = acc[mi][ni][p * 2 + 0];
                        const float x1b = acc[mi][ni][p * 2 + 1];
                        const float x2a = smT[d * 132 + r];
                        const float x2b = smT[(d + 1) * 132 + r];
                        const float2 cl = *(const float2*)(cosb + (size_t)s * HD + d);
                        const float2 sl = *(const float2*)(sinb + (size_t)s * HD + d);
                        const float2 chh = *(const float2*)(cosb + (size_t)s * HD + d + 64);
                        const float2 shh = *(const float2*)(sinb + (size_t)s * HD + d + 64);
                        __half2 lo = __floats2half2_rn(x1a * cl.x - x2a * sl.x,
                                                       x1b * cl.y - x2b * sl.y);
                        __half2 hi = __floats2half2_rn(x2a * chh.x + x1a * shh.x,
                                                       x2b * chh.y + x1b * shh.y);
                        __half* o = outp + (size_t)s * nh * HD + h * HD + d;
                        *reinterpret_cast<__half2*>(o)      = lo;
                        *reinterpret_cast<__half2*>(o + 64) = hi;
                    }
                }
        }
    } else {
        // ---- V transpose epilogue: vt[h][d][s] = proj[s][d] ----
        #pragma unroll
        for (int pass = 0; pass < 2; pass++) {
            const bool writer = (pass == 0) ? (wn < 2) : (wn >= 2);
            if (writer) {
                #pragma unroll
                for (int mi = 0; mi < 2; mi++)
                    #pragma unroll
                    for (int ni = 0; ni < 4; ni++) {
                        const int dl = (wn - 2 * pass) * 32 + ni * 8 + 2 * l4; // 0..63
                        #pragma unroll
                        for (int p = 0; p < 2; p++) {
                            const int r = wm * 32 + mi * 16 + t4 + p * 8;
                            smT[dl * 132 + r]       = acc[mi][ni][p * 2 + 0];
                            smT[(dl + 1) * 132 + r] = acc[mi][ni][p * 2 + 1];
                        }
                    }
            }
            __syncthreads();
            #pragma unroll 4
            for (int l = 0; l < 16; l++) {
                const int e  = l * 512 + tid;
                const int dl = e >> 7;
                const int sl = e & 127;
                vt[(size_t)h * HD * S_LEN + (size_t)(dl + pass * 64) * S_LEN
                   + by * 128 + sl] = __float2half_rn(smT[dl * 132 + sl]);
            }
            __syncthreads();
        }
    }
}

// ---------------------------------------------------------------------------
// Fused fp32 -> fp16 conversion of all 5 inputs in one launch.
// Segment boundaries in float4 units.
// ---------------------------------------------------------------------------
#define CVT_B0 2097152    // hs   (2048*4096/4)
#define CVT_B1 6291456    // + wq (4096*4096/4)
#define CVT_B2 7340032    // + wk (1024*4096/4)
#define CVT_B3 8388608    // + wv
#define CVT_B4 12582912   // + wo
__global__ void cvt_all(const float4* __restrict__ hs, const float4* __restrict__ wq,
                        const float4* __restrict__ wk, const float4* __restrict__ wv,
                        const float4* __restrict__ wo,
                        __half2* __restrict__ hsh, __half2* __restrict__ wqh,
                        __half2* __restrict__ wkh, __half2* __restrict__ wvh,
                        __half2* __restrict__ woh)
{
    const int i = blockIdx.x * blockDim.x + threadIdx.x;
    if (i >= CVT_B4) return;
    const float4* src; __half2* dst; int j;
    if (i < CVT_B0)      { src = hs; dst = hsh; j = i; }
    else if (i < CVT_B1) { src = wq; dst = wqh; j = i - CVT_B0; }
    else if (i < CVT_B2) { src = wk; dst = wkh; j = i - CVT_B1; }
    else if (i < CVT_B3) { src = wv; dst = wvh; j = i - CVT_B2; }
    else                 { src = wo; dst = woh; j = i - CVT_B3; }
    float4 v = src[j];
    dst[j * 2 + 0] = __floats2half2_rn(v.x, v.y);
    dst[j * 2 + 1] = __floats2half2_rn(v.z, v.w);
}

// ---------------------------------------------------------------------------
// Causal softmax, float4 IO. Writes W fp32 only up to the 128-block containing
// q (beyond is pre-zeroed by the scores kernel) + fp16 Wh clipped likewise.
// ---------------------------------------------------------------------------
__global__ __launch_bounds__(256) void softmax_causal(float* __restrict__ W,
                                                      __half* __restrict__ Wh)
{
    const int q = blockIdx.x;
    const int h = blockIdx.y;
    const long long off = ((long long)h * S_LEN + q) * S_LEN;
    float4* row4  = reinterpret_cast<float4*>(W + off);
    __half2* rowh2 = reinterpret_cast<__half2*>(Wh + off);
    const int L = q + 1;
    const int clip4 = (((q >> 7) + 1) << 7) >> 2;   // write bound in float4 units
    const int tid = threadIdx.x;
    __shared__ float red[32];

    float4 va[2];
    const float NEGINF = -3.402823e38f;

    float mx = NEGINF;
    #pragma unroll
    for (int j = 0; j < 2; j++) {
        const int iv = tid + j * 256;
        const int k0 = iv * 4;
        if (k0 < L) {
            float4 v = row4[iv];
            va[j] = v;
            mx = fmaxf(mx, v.x);
            if (k0 + 1 < L) mx = fmaxf(mx, v.y);
            if (k0 + 2 < L) mx = fmaxf(mx, v.z);
            if (k0 + 3 < L) mx = fmaxf(mx, v.w);
        }
    }
    #pragma unroll
    for (int o = 16; o; o >>= 1) mx = fmaxf(mx, __shfl_xor_sync(0xffffffffu, mx, o));
    if ((tid & 31) == 0) red[tid >> 5] = mx;
    __syncthreads();
    if (tid < 32) {
        float w2 = (tid < 8) ? red[tid] : NEGINF;
        #pragma unroll
        for (int o = 4; o; o >>= 1) w2 = fmaxf(w2, __shfl_xor_sync(0xffffffffu, w2, o));
        if (tid == 0) red[0] = w2;
    }
    __syncthreads();
    mx = red[0];
    __syncthreads();

    float s = 0.f;
    #pragma unroll
    for (int j = 0; j < 2; j++) {
        const int iv = tid + j * 256;
        const int k0 = iv * 4;
        float4 e = make_float4(0.f, 0.f, 0.f, 0.f);
        if (k0 < L) {
            e.x = expf(va[j].x - mx);
            if (k0 + 1 < L) e.y = expf(va[j].y - mx);
            if (k0 + 2 < L) e.z = expf(va[j].z - mx);
            if (k0 + 3 < L) e.w = expf(va[j].w - mx);
            s += e.x + e.y + e.z + e.w;
        }
        va[j] = e;
    }
    #pragma unroll
    for (int o = 16; o; o >>= 1) s += __shfl_xor_sync(0xffffffffu, s, o);
    if ((tid & 31) == 0) red[tid >> 5] = s;
    __syncthreads();
    if (tid < 32) {
        float w2 = (tid < 8) ? red[tid] : 0.f;
        #pragma unroll
        for (int o = 4; o; o >>= 1) w2 += __shfl_xor_sync(0xffffffffu, w2, o);
        if (tid == 0) red[0] = w2;
    }
    __syncthreads();
    const float inv = 1.f / red[0];

    #pragma unroll
    for (int j = 0; j < 2; j++) {
        const int iv = tid + j * 256;
        if (iv < clip4) {
            float4 o4 = make_float4(va[j].x * inv, va[j].y * inv,
                                    va[j].z * inv, va[j].w * inv);
            row4[iv] = o4;
            rowh2[iv * 2 + 0] = __floats2half2_rn(o4.x, o4.y);
            rowh2[iv * 2 + 1] = __floats2half2_rn(o4.z, o4.w);
        }
    }
}

// ---------------------------------------------------------------------------
extern "C" void kernel_launch(void* const* d_in, const int* in_sizes, int n_in,
                              void* d_out, int out_size)
{
    const float* hs   = (const float*)d_in[0];
    const float* wq   = (const float*)d_in[1];
    const float* wk   = (const float*)d_in[2];
    const float* wv   = (const float*)d_in[3];
    const float* wo   = (const float*)d_in[4];
    const float* cosb = (const float*)d_in[5];
    const float* sinb = (const float*)d_in[6];
    (void)in_sizes; (void)n_in;

    float* out = (float*)d_out;

    const long long OUT_ELEMS = (long long)S_LEN * NH * HD;
    const long long W_ELEMS   = (long long)NH * S_LEN * S_LEN;

    __half *hsh, *wqh, *wkh, *wvh, *woh, *qh, *kh, *vtp, *aoh, *whp;
    float  *wsc;
    cudaGetSymbolAddress((void**)&hsh, g_hsh);
    cudaGetSymbolAddress((void**)&wqh, g_wqh);
    cudaGetSymbolAddress((void**)&wkh, g_wkh);
    cudaGetSymbolAddress((void**)&wvh, g_wvh);
    cudaGetSymbolAddress((void**)&woh, g_woh);
    cudaGetSymbolAddress((void**)&qh,  g_qh);
    cudaGetSymbolAddress((void**)&kh,  g_kh);
    cudaGetSymbolAddress((void**)&vtp, g_vt);
    cudaGetSymbolAddress((void**)&aoh, g_aoh);
    cudaGetSymbolAddress((void**)&whp, g_wh);
    cudaGetSymbolAddress((void**)&wsc, g_w_scratch);

    float* W = ((long long)out_size >= OUT_ELEMS + W_ELEMS) ? (out + OUT_ELEMS) : wsc;

    static int attr_done = 0;
    if (!attr_done) {
        cudaFuncSetAttribute(mm_f16,   cudaFuncAttributeMaxDynamicSharedMemorySize, DYN_SMEM);
        cudaFuncSetAttribute(qkv_rope, cudaFuncAttributeMaxDynamicSharedMemorySize, DYN_SMEM);
        attr_done = 1;
    }

    // 0) fp16 conversion of all inputs, one launch
    cvt_all<<<(CVT_B4 + 255) / 256, 256>>>(
        (const float4*)hs, (const float4*)wq, (const float4*)wk,
        (const float4*)wv, (const float4*)wo,
        (__half2*)hsh, (__half2*)wqh, (__half2*)wkh, (__half2*)wvh, (__half2*)woh);

    // 1) Merged QKV projections + RoPE + V-transpose
    qkv_rope<<<dim3(48, S_LEN / BM), 512, DYN_SMEM>>>(hsh, wqh, wkh, wvh,
                                                      qh, kh, vtp, cosb, sinb);

    // 2) Scores: Q_h @ K_{h/4}^T * scaling -> fp32 W (skipped CTAs zero-fill)
    mm_f16<<<dim3(S_LEN / BN, S_LEN / BM, NH), 512, DYN_SMEM>>>(qh, kh, W,
        HD, NH * HD, NKV * HD, S_LEN,
        HD, HD, 2, (long long)S_LEN * S_LEN, SCALING, 1, 0);

    // 3) Softmax: W fp32 (clipped; upper blocks pre-zeroed) + Wh fp16
    softmax_causal<<<dim3(S_LEN, NH), 256>>>(W, whp);

    // 4) attn_out = W_h @ (V^T_{h/4})^T, K clipped -> fp16
    mm_f16<<<dim3(1, S_LEN / BM, NH), 512, DYN_SMEM>>>(whp, vtp, aoh,
        S_LEN, S_LEN, S_LEN, NH * HD,
        (long long)S_LEN * S_LEN, (long long)HD * S_LEN, 2, HD, 1.f, 2, 1);

    // 5) out = attn_out @ wo^T -> fp32
    mm_f16<<<dim3(NH * HD / BN, S_LEN / BM), 512, DYN_SMEM>>>(aoh, woh, out,
        HDIM, HDIM, HDIM, NH * HD, 0, 0, 0, 0, 1.f, 0, 0);
}